// round 13
// baseline (speedup 1.0000x reference)
#include <cuda_runtime.h>
#include <cuda_fp16.h>
#include <cstdint>
#include <math.h>

// ---------------------------------------------------------------------------
// Problem constants
// ---------------------------------------------------------------------------
#define BB 8192
#define NN 64
#define CC 8
#define DD (NN * CC)        // 512
#define HP 1024
#define HS 512
#define BD_ELEMS (BB * DD)  // 4,194,304
#define BN_ELEMS (BB * NN)  // 524,288

// ---------------------------------------------------------------------------
// Scratch (allocation-free: __device__ globals)
// ---------------------------------------------------------------------------
__device__ __half g_a_hi[BB * HP];
__device__ __half g_a_lo[BB * HP];
__device__ __half g_b_hi[BB * HP];
__device__ __half g_b_lo[BB * HP];
__device__ __half g_xh[BB * DD];
__device__ float  g_s1[BB * HS];
__device__ float  g_bias_l1[HP + HS];   // pb1 ++ sb1

// Transposed + split weights, packed (Bt[n][k] layout), fp16 hi/lo.
#define OF_PW1 0
#define OF_SW1 524288
#define OF_PW2 786432
#define OF_PW3 1835008
#define OF_PW4 2883584
#define WT_TOTAL 3407872
__device__ __half g_wt_hi[WT_TOTAL];
__device__ __half g_wt_lo[WT_TOTAL];

// ---------------------------------------------------------------------------
// Threefry-2x32-20 (JAX)
// ---------------------------------------------------------------------------
struct TFK { unsigned a, b; };

__host__ __device__ constexpr unsigned tf_rotl(unsigned v, int r) {
    return (v << r) | (v >> (32 - r));
}

__host__ __device__ constexpr TFK tf2x32(unsigned k0, unsigned k1,
                                         unsigned x0, unsigned x1) {
    unsigned k2 = k0 ^ k1 ^ 0x1BD11BDAu;
    x0 += k0; x1 += k1;
    x0 += x1; x1 = tf_rotl(x1, 13); x1 ^= x0;
    x0 += x1; x1 = tf_rotl(x1, 15); x1 ^= x0;
    x0 += x1; x1 = tf_rotl(x1, 26); x1 ^= x0;
    x0 += x1; x1 = tf_rotl(x1,  6); x1 ^= x0;
    x0 += k1; x1 += k2 + 1u;
    x0 += x1; x1 = tf_rotl(x1, 17); x1 ^= x0;
    x0 += x1; x1 = tf_rotl(x1, 29); x1 ^= x0;
    x0 += x1; x1 = tf_rotl(x1, 16); x1 ^= x0;
    x0 += x1; x1 = tf_rotl(x1, 24); x1 ^= x0;
    x0 += k2; x1 += k0 + 2u;
    x0 += x1; x1 = tf_rotl(x1, 13); x1 ^= x0;
    x0 += x1; x1 = tf_rotl(x1, 15); x1 ^= x0;
    x0 += x1; x1 = tf_rotl(x1, 26); x1 ^= x0;
    x0 += x1; x1 = tf_rotl(x1,  6); x1 ^= x0;
    x0 += k0; x1 += k1 + 3u;
    x0 += x1; x1 = tf_rotl(x1, 17); x1 ^= x0;
    x0 += x1; x1 = tf_rotl(x1, 29); x1 ^= x0;
    x0 += x1; x1 = tf_rotl(x1, 16); x1 ^= x0;
    x0 += x1; x1 = tf_rotl(x1, 24); x1 ^= x0;
    x0 += k1; x1 += k2 + 4u;
    x0 += x1; x1 = tf_rotl(x1, 13); x1 ^= x0;
    x0 += x1; x1 = tf_rotl(x1, 15); x1 ^= x0;
    x0 += x1; x1 = tf_rotl(x1, 26); x1 ^= x0;
    x0 += x1; x1 = tf_rotl(x1,  6); x1 ^= x0;
    x0 += k2; x1 += k0 + 5u;
    return TFK{x0, x1};
}

constexpr unsigned KA0 = tf2x32(0u, 42u, 0u, 0u).a;
constexpr unsigned KA1 = tf2x32(0u, 42u, 0u, 0u).b;
constexpr unsigned KB0 = tf2x32(0u, 42u, 0u, 1u).a;
constexpr unsigned KB1 = tf2x32(0u, 42u, 0u, 1u).b;
constexpr unsigned KG0 = tf2x32(0u, 42u, 0u, 2u).a;
constexpr unsigned KG1 = tf2x32(0u, 42u, 0u, 2u).b;

__device__ __forceinline__ float jax_u01(unsigned k0, unsigned k1, unsigned idx) {
    TFK r = tf2x32(k0, k1, 0u, idx);
    unsigned bits = r.a ^ r.b;
    float f = __uint_as_float((bits >> 9) | 0x3f800000u) - 1.0f;
    f = f + 1e-8f;
    return fmaxf(1e-8f, f);
}

// ---------------------------------------------------------------------------
// Helpers
// ---------------------------------------------------------------------------
__device__ __forceinline__ uint32_t smem_u32(const void* p) {
    uint32_t a;
    asm("{ .reg .u64 t; cvta.to.shared.u64 t, %1; cvt.u32.u64 %0, t; }"
        : "=r"(a) : "l"(p));
    return a;
}

#define CP16(dst_u32, src_ptr) \
    asm volatile("cp.async.cg.shared.global [%0], [%1], 16;" \
                 :: "r"(dst_u32), "l"(src_ptr) : "memory")
#define CP_COMMIT() asm volatile("cp.async.commit_group;" ::: "memory")
#define CP_WAIT(n)  asm volatile("cp.async.wait_group %0;" :: "n"(n) : "memory")

__device__ __forceinline__ void mma16(float* d, const uint32_t* a,
                                      const uint32_t* b) {
    asm volatile(
        "mma.sync.aligned.m16n8k16.row.col.f32.f16.f16.f32 "
        "{%0,%1,%2,%3}, {%4,%5,%6,%7}, {%8,%9}, {%0,%1,%2,%3};"
        : "+f"(d[0]), "+f"(d[1]), "+f"(d[2]), "+f"(d[3])
        : "r"(a[0]), "r"(a[1]), "r"(a[2]), "r"(a[3]), "r"(b[0]), "r"(b[1]));
}

__device__ __forceinline__ void ldsm_x4(uint32_t* r, uint32_t addr) {
    asm volatile(
        "ldmatrix.sync.aligned.m8n8.x4.shared.b16 {%0,%1,%2,%3}, [%4];"
        : "=r"(r[0]), "=r"(r[1]), "=r"(r[2]), "=r"(r[3]) : "r"(addr));
}

__device__ __forceinline__ void split_h(float y, __half& h, __half& l) {
    h = __float2half_rn(y);
    l = __float2half_rn(y - __half2float(h));
}

// ---------------------------------------------------------------------------
// fp16-split GEMM mainloop. BM=128, BN=64, BK=32, 256 thr, warps 2x4,
// warp tile 64x16 (acc=32 regs -> 3 CTAs/SM). Packed 64B rows + XOR
// swizzle, 3 stages, one barrier per chunk, prefetch distance 2.
// ---------------------------------------------------------------------------
#define TILE_A 8192                     // 128 rows x 64 bytes
#define TILE_BT 4096                    // 64 rows x 64 bytes
#define T_AH 0
#define T_AL TILE_A
#define T_BH (2 * TILE_A)
#define T_BL (2 * TILE_A + TILE_BT)
#define STAGE_B (2 * TILE_A + 2 * TILE_BT)   // 24576 bytes / stage
#define GEMM_SMEM (3 * STAGE_B)              // 73728 bytes

template <bool AEX>
__device__ __forceinline__ void issue_chunk_h(
    uint32_t smb, int c,
    const __half* __restrict__ A_hi, const __half* __restrict__ A_lo,
    const __half* __restrict__ B_hi, const __half* __restrict__ B_lo,
    int K, int bm0, int bn0, int tid) {
    const int k0 = c * 32;
    const uint32_t sb = smb + (uint32_t)((c % 3) * STAGE_B);
    // A: 128 rows x 4 units (hi, and lo unless AEX)
#pragma unroll
    for (int i = 0; i < 2; i++) {
        const int f = tid + i * 256;
        const int row = f >> 2;
        const int q = f & 3;
        const uint32_t doff =
            (uint32_t)(row * 64 + ((q ^ ((row >> 1) & 3)) * 16));
        CP16(sb + T_AH + doff, A_hi + (size_t)(bm0 + row) * K + k0 + q * 8);
        if (!AEX)
            CP16(sb + T_AL + doff,
                 A_lo + (size_t)(bm0 + row) * K + k0 + q * 8);
    }
    // B: 64 rows x 4 units, hi + lo (one unit each per thread)
    {
        const int row = tid >> 2;
        const int q = tid & 3;
        const uint32_t doff =
            (uint32_t)(row * 64 + ((q ^ ((row >> 1) & 3)) * 16));
        CP16(sb + T_BH + doff, B_hi + (size_t)(bn0 + row) * K + k0 + q * 8);
        CP16(sb + T_BL + doff, B_lo + (size_t)(bn0 + row) * K + k0 + q * 8);
    }
    CP_COMMIT();
}

template <bool AEX>
__device__ __forceinline__ void gemm_mainloop(
    uint32_t smb, const __half* __restrict__ A_hi,
    const __half* __restrict__ A_lo, const __half* __restrict__ Bt_hi,
    const __half* __restrict__ Bt_lo, int K, int bm0, int bn0, int tid,
    float acc[4][2][4]) {
    const int l = tid & 31;
    const int warp = tid >> 5;
    const int wm = warp >> 2;          // 0..1   (64 rows each)
    const int wn = warp & 3;           // 0..3   (16 cols each)
    const int NC = K >> 5;

    issue_chunk_h<AEX>(smb, 0, A_hi, A_lo, Bt_hi, Bt_lo, K, bm0, bn0, tid);
    if (NC > 1)
        issue_chunk_h<AEX>(smb, 1, A_hi, A_lo, Bt_hi, Bt_lo, K, bm0, bn0, tid);

    const int swz = (l >> 1) & 3;
    const uint32_t arow = (uint32_t)((wm * 64 + (l & 15)) * 64);
    const int acb = l >> 4;            // 0 or 1
    const uint32_t brow =
        (uint32_t)((wn * 16 + ((l >> 4) & 1) * 8 + (l & 7)) * 64);
    const int bcb = (l >> 3) & 1;

    for (int c = 0; c < NC; c++) {
        if (c + 1 < NC) {
            CP_WAIT(1);
        } else {
            CP_WAIT(0);
        }
        __syncthreads();
        if (c + 2 < NC)
            issue_chunk_h<AEX>(smb, c + 2, A_hi, A_lo, Bt_hi, Bt_lo, K, bm0,
                               bn0, tid);

        const uint32_t stage = smb + (uint32_t)((c % 3) * STAGE_B);
        const uint32_t baseAh = stage + T_AH + arow;
        const uint32_t baseAl = stage + T_AL + arow;
        const uint32_t baseBh = stage + T_BH + brow;
        const uint32_t baseBl = stage + T_BL + brow;

#pragma unroll
        for (int ks = 0; ks < 2; ks++) {
            const uint32_t aco = (uint32_t)(((ks * 2 + acb) ^ swz) * 16);
            const uint32_t bco = (uint32_t)(((ks * 2 + bcb) ^ swz) * 16);
            uint32_t bh[2][2], bl[2][2];
            {
                uint32_t t[4];
                ldsm_x4(t, baseBh + bco);
                bh[0][0] = t[0]; bh[0][1] = t[1];
                bh[1][0] = t[2]; bh[1][1] = t[3];
                ldsm_x4(t, baseBl + bco);
                bl[0][0] = t[0]; bl[0][1] = t[1];
                bl[1][0] = t[2]; bl[1][1] = t[3];
            }
#pragma unroll
            for (int mf = 0; mf < 4; mf++) {
                uint32_t ah[4], al[4];
                ldsm_x4(ah, baseAh + (uint32_t)(mf * 16 * 64) + aco);
                if (!AEX)
                    ldsm_x4(al, baseAl + (uint32_t)(mf * 16 * 64) + aco);
#pragma unroll
                for (int nf = 0; nf < 2; nf++) {
                    mma16(acc[mf][nf], ah, bh[nf]);
                    mma16(acc[mf][nf], ah, bl[nf]);
                    if (!AEX) mma16(acc[mf][nf], al, bh[nf]);
                }
            }
        }
    }
    __syncthreads();
}

// Epilogue for relu+split / fp32 outputs
template <int OMODE>   // 0 = relu+split, 1 = fp32, 2 = mixed L1
__device__ __forceinline__ void gemm_epilogue(
    float acc[4][2][4], const float* __restrict__ bias,
    __half* __restrict__ O_hi, __half* __restrict__ O_lo,
    float* __restrict__ Of, int Nout, int bm0, int bn0, int tid) {
    const int l = tid & 31;
    const int warp = tid >> 5;
    const int wm = warp >> 2;
    const int wn = warp & 3;
    const int rA = l >> 2;
    const int cK = l & 3;
    const bool f32_region = (OMODE == 1) || (OMODE == 2 && bn0 >= HP);
    const int ow = (OMODE == 2) ? (f32_region ? HS : HP) : Nout;
    const int cbase = (OMODE == 2 && f32_region) ? (bn0 - HP) : bn0;

#pragma unroll
    for (int nf = 0; nf < 2; nf++) {
        const int gcol = bn0 + wn * 16 + nf * 8 + 2 * cK;
        const int col = cbase + wn * 16 + nf * 8 + 2 * cK;
        const float2 bv = *reinterpret_cast<const float2*>(bias + gcol);
#pragma unroll
        for (int mf = 0; mf < 4; mf++) {
            const int ra = bm0 + wm * 64 + mf * 16 + rA;
            float y[4];
            y[0] = acc[mf][nf][0] + bv.x;
            y[1] = acc[mf][nf][1] + bv.y;
            y[2] = acc[mf][nf][2] + bv.x;
            y[3] = acc[mf][nf][3] + bv.y;
            if (OMODE != 1) {
#pragma unroll
                for (int r = 0; r < 4; r++) y[r] = fmaxf(y[r], 0.0f);
            }
            if (!f32_region && OMODE != 1) {
                __half h[4], lo[4];
#pragma unroll
                for (int r = 0; r < 4; r++) split_h(y[r], h[r], lo[r]);
                *reinterpret_cast<__half2*>(O_hi + (size_t)ra * ow + col) =
                    __halves2half2(h[0], h[1]);
                *reinterpret_cast<__half2*>(O_hi + (size_t)(ra + 8) * ow + col) =
                    __halves2half2(h[2], h[3]);
                *reinterpret_cast<__half2*>(O_lo + (size_t)ra * ow + col) =
                    __halves2half2(lo[0], lo[1]);
                *reinterpret_cast<__half2*>(O_lo + (size_t)(ra + 8) * ow + col) =
                    __halves2half2(lo[2], lo[3]);
            } else {
                *reinterpret_cast<float2*>(Of + (size_t)ra * ow + col) =
                    make_float2(y[0], y[1]);
                *reinterpret_cast<float2*>(Of + (size_t)(ra + 8) * ow + col) =
                    make_float2(y[2], y[3]);
            }
        }
    }
}

// Plain GEMM kernels (L1 mixed, L3 split, L4 fp32)
template <bool AEX, int OMODE>
__global__ void __launch_bounds__(256, 3)
gemm_h(const __half* __restrict__ A_hi, const __half* __restrict__ A_lo,
       const __half* __restrict__ Bt_hi, const __half* __restrict__ Bt_lo,
       const float* __restrict__ bias,
       __half* __restrict__ O_hi, __half* __restrict__ O_lo,
       float* __restrict__ Of,
       int K, int Nout) {
    extern __shared__ __half smh[];
    const uint32_t smb = smem_u32(smh);
    const int tid = threadIdx.x;
    const int bm0 = blockIdx.y * 128;
    const int bn0 = blockIdx.x * 64;

    float acc[4][2][4];
#pragma unroll
    for (int mf = 0; mf < 4; mf++)
#pragma unroll
        for (int nf = 0; nf < 2; nf++)
#pragma unroll
            for (int r = 0; r < 4; r++) acc[mf][nf][r] = 0.0f;

    gemm_mainloop<AEX>(smb, A_hi, A_lo, Bt_hi, Bt_lo, K, bm0, bn0, tid, acc);
    gemm_epilogue<OMODE>(acc, bias, O_hi, O_lo, Of, Nout, bm0, bn0, tid);
}

// ---------------------------------------------------------------------------
// Selector head body (3-stage cp.async pipeline) — runs inside fused kernel.
// ---------------------------------------------------------------------------
__device__ __forceinline__ void sel_head_body(
    char* smc, int bm0, int tid,
    const float* __restrict__ A, const float* __restrict__ B,
    const float* __restrict__ bias, float* __restrict__ C) {
    float (*As)[32][20] = reinterpret_cast<float (*)[32][20]>(smc);
    float (*Bs)[16][64] = reinterpret_cast<float (*)[16][64]>(smc + 3 * 32 * 20 * 4);

    const int tx = tid & 15;
    const int ty = tid >> 4;
    const int K = HS, N = NN;
    const int NC = K / 16;

    const uint32_t asb = smem_u32(As);
    const uint32_t bsb = smem_u32(Bs);

    auto issue = [&](int c) {
        const int s = c % 3;
        const int k0 = c * 16;
        if (tid < 128) {
            const int row = tid >> 2;
            const int q = tid & 3;
            CP16(asb + (uint32_t)(((s * 32 + row) * 20 + q * 4) * 4),
                 A + (size_t)(bm0 + row) * K + k0 + q * 4);
        }
        {
            const int kr = tid >> 4;
            const int q = tid & 15;
            CP16(bsb + (uint32_t)(((s * 16 + kr) * 64 + q * 4) * 4),
                 B + (size_t)(k0 + kr) * N + q * 4);
        }
        CP_COMMIT();
    };

    float acc[2][4] = {{0.f, 0.f, 0.f, 0.f}, {0.f, 0.f, 0.f, 0.f}};

    issue(0);
    issue(1);

    for (int c = 0; c < NC; c++) {
        const int s = c % 3;
        if (c + 1 < NC) CP_WAIT(1); else CP_WAIT(0);
        __syncthreads();
        if (c + 2 < NC) issue(c + 2);

#pragma unroll
        for (int k = 0; k < 16; k++) {
            float a0 = As[s][ty * 2][k];
            float a1 = As[s][ty * 2 + 1][k];
            float4 bv = *reinterpret_cast<const float4*>(&Bs[s][k][tx * 4]);
            acc[0][0] = fmaf(a0, bv.x, acc[0][0]);
            acc[0][1] = fmaf(a0, bv.y, acc[0][1]);
            acc[0][2] = fmaf(a0, bv.z, acc[0][2]);
            acc[0][3] = fmaf(a0, bv.w, acc[0][3]);
            acc[1][0] = fmaf(a1, bv.x, acc[1][0]);
            acc[1][1] = fmaf(a1, bv.y, acc[1][1]);
            acc[1][2] = fmaf(a1, bv.z, acc[1][2]);
            acc[1][3] = fmaf(a1, bv.w, acc[1][3]);
        }
    }

    float4 bvec = *reinterpret_cast<const float4*>(bias + tx * 4);
    float bias4[4] = {bvec.x, bvec.y, bvec.z, bvec.w};
#pragma unroll
    for (int i = 0; i < 2; i++) {
        float4 v;
        float* vp = &v.x;
#pragma unroll
        for (int j = 0; j < 4; j++) {
            float cv = acc[i][j] + bias4[j];
            vp[j] = 1.0f / (1.0f + expf(-cv));
        }
        *reinterpret_cast<float4*>(
            C + (size_t)(bm0 + ty * 2 + i) * N + tx * 4) = v;
    }
}

// ---------------------------------------------------------------------------
// FUSED gemm2 + selector head. grid = (16, 64 + 16):
//   y <  64: gemm2 tile; y >= 64: head block hb = (y-64)*16 + x in [0,256)
// ---------------------------------------------------------------------------
__global__ void __launch_bounds__(256, 3)
gemm2_head_kernel(const __half* __restrict__ A_hi,
                  const __half* __restrict__ A_lo,
                  const __half* __restrict__ Bt_hi,
                  const __half* __restrict__ Bt_lo,
                  const float* __restrict__ bias,
                  __half* __restrict__ O_hi, __half* __restrict__ O_lo,
                  const float* __restrict__ s1, const float* __restrict__ sw2,
                  const float* __restrict__ sb2, float* __restrict__ P) {
    extern __shared__ char smc[];
    const int tid = threadIdx.x;

    if (blockIdx.y >= 64) {
        const int hb = (blockIdx.y - 64) * 16 + blockIdx.x;   // 0..255
        sel_head_body(smc, hb * 32, tid, s1, sw2, sb2, P);
        return;
    }

    const uint32_t smb = smem_u32(smc);
    const int bm0 = blockIdx.y * 128;
    const int bn0 = blockIdx.x * 64;

    float acc[4][2][4];
#pragma unroll
    for (int mf = 0; mf < 4; mf++)
#pragma unroll
        for (int nf = 0; nf < 2; nf++)
#pragma unroll
            for (int r = 0; r < 4; r++) acc[mf][nf][r] = 0.0f;

    gemm_mainloop<false>(smb, A_hi, A_lo, Bt_hi, Bt_lo, HP, bm0, bn0, tid, acc);
    gemm_epilogue<0>(acc, bias, O_hi, O_lo, nullptr, HP, bm0, bn0, tid);
}

// ---------------------------------------------------------------------------
// MERGED prep kernel
// ---------------------------------------------------------------------------
__global__ void __launch_bounds__(256)
prep_kernel(const float* __restrict__ x, __half* __restrict__ xh,
            const float* __restrict__ pb1, const float* __restrict__ sb1,
            float* __restrict__ bias_l1,
            const float* __restrict__ pw1, const float* __restrict__ sw1,
            const float* __restrict__ pw2, const float* __restrict__ pw3,
            const float* __restrict__ pw4,
            __half* __restrict__ bt_hi, __half* __restrict__ bt_lo) {
    if (blockIdx.x < 2048) {
        const int t = blockIdx.x * 256 + threadIdx.x;
        const float4 a = *reinterpret_cast<const float4*>(x + (size_t)t * 8);
        const float4 b = *reinterpret_cast<const float4*>(x + (size_t)t * 8 + 4);
        __half2 o[4];
        o[0] = __halves2half2(__float2half_rn(a.x), __float2half_rn(a.y));
        o[1] = __halves2half2(__float2half_rn(a.z), __float2half_rn(a.w));
        o[2] = __halves2half2(__float2half_rn(b.x), __float2half_rn(b.y));
        o[3] = __halves2half2(__float2half_rn(b.z), __float2half_rn(b.w));
        *reinterpret_cast<uint4*>(xh + (size_t)t * 8) =
            *reinterpret_cast<uint4*>(o);
        if (t < HP + HS)
            bias_l1[t] = (t < HP) ? pb1[t] : sb1[t - HP];
        return;
    }

    const int b = blockIdx.x - 2048;
    const float* W;
    int off, K, N, lb;
    if (b < 512)        { W = pw1; off = OF_PW1; K = 512;  N = 1024; lb = b; }
    else if (b < 768)   { W = sw1; off = OF_SW1; K = 512;  N = 512;  lb = b - 512; }
    else if (b < 1792)  { W = pw2; off = OF_PW2; K = 1024; N = 1024; lb = b - 768; }
    else if (b < 2816)  { W = pw3; off = OF_PW3; K = 1024; N = 1024; lb = b - 1792; }
    else                { W = pw4; off = OF_PW4; K = 1024; N = 512;  lb = b - 2816; }
    const int kt = K >> 5;
    const int kb = (lb % kt) * 32;
    const int nb = (lb / kt) * 32;

    __shared__ float t[32][33];
    const int tx = threadIdx.x & 31;
    const int ty = threadIdx.x >> 5;
#pragma unroll
    for (int r = ty; r < 32; r += 8)
        t[r][tx] = W[(size_t)(kb + r) * N + nb + tx];
    __syncthreads();
#pragma unroll
    for (int r = ty; r < 32; r += 8) {
        float wv = t[tx][r];
        __half h, lo;
        split_h(wv, h, lo);
        size_t o = (size_t)off + (size_t)(nb + r) * K + kb + tx;
        bt_hi[o] = h;
        bt_lo[o] = lo;
    }
}

// ---------------------------------------------------------------------------
// Fused elementwise tail (+ truth_x passthrough)
// ---------------------------------------------------------------------------
__device__ __forceinline__ void gs8(const float* l, const float* g, float* xt) {
    float m = l[0];
#pragma unroll
    for (int c = 1; c < 8; c++) m = fmaxf(m, l[c]);
    float e[8], s = 0.0f;
#pragma unroll
    for (int c = 0; c < 8; c++) { e[c] = expf(l[c] - m); s += e[c]; }
    float t[8];
#pragma unroll
    for (int c = 0; c < 8; c++) {
        float pr = e[c] / s;
        pr = 0.9f * pr + 0.0125f;
        t[c] = (logf(pr) + g[c]) / 0.7f;
    }
    float m2 = t[0];
#pragma unroll
    for (int c = 1; c < 8; c++) m2 = fmaxf(m2, t[c]);
    float e2[8], s2 = 0.0f;
#pragma unroll
    for (int c = 0; c < 8; c++) { e2[c] = expf(t[c] - m2); s2 += e2[c]; }
#pragma unroll
    for (int c = 0; c < 8; c++) xt[c] = e2[c] / s2;
}

__global__ void finalize_kernel(const float* __restrict__ x,
                                const float* __restrict__ Pm,
                                const float* __restrict__ W,
                                const float* __restrict__ truth,
                                float* __restrict__ out_truth,
                                float* __restrict__ xcf) {
    const int b = blockIdx.x;
    const int n = threadIdx.x;
    __shared__ float sh_cst, sh_incr;

    const size_t base = (size_t)b * DD + n * CC;

    *reinterpret_cast<float4*>(out_truth + base) =
        *reinterpret_cast<const float4*>(truth + base);
    *reinterpret_cast<float4*>(out_truth + base + 4) =
        *reinterpret_cast<const float4*>(truth + base + 4);

    float4 xa = *reinterpret_cast<const float4*>(x + base);
    float4 xb = *reinterpret_cast<const float4*>(x + base + 4);
    float4 wa = *reinterpret_cast<const float4*>(W + base);
    float4 wb = *reinterpret_cast<const float4*>(W + base + 4);
    float xv[8] = {xa.x, xa.y, xa.z, xa.w, xb.x, xb.y, xb.z, xb.w};
    float Wv[8] = {wa.x, wa.y, wa.z, wa.w, wb.x, wb.y, wb.z, wb.w};

    const unsigned i = (unsigned)(b * NN + n);
    const float P = Pm[i];

    float ua = jax_u01(KA0, KA1, i);
    float ub = jax_u01(KB0, KB1, i);
    float ea = expf(-logf(-logf(ua)));
    float eb = expf(-logf(-logf(ub)));
    float no = P * ea / 0.7f;
    float de = no + (1.0f - P) * eb / 0.7f;
    float probs = no / de;

    float g[8];
#pragma unroll
    for (int c = 0; c < 8; c++) {
        float u = jax_u01(KG0, KG1, i * 8u + (unsigned)c);
        g[c] = -logf(-logf(u));
    }

    int curr = 0;
    {
        float m = xv[0];
#pragma unroll
        for (int c = 1; c < 8; c++)
            if (xv[c] > m) { m = xv[c]; curr = c; }
    }

    if (n == 2) {
        float xt_par[8];
        gs8(Wv, g, xt_par);
        int am = 0;
        float m = probs * xt_par[0] + (1.0f - probs) * xv[0];
#pragma unroll
        for (int c = 1; c < 8; c++) {
            float v = probs * xt_par[c] + (1.0f - probs) * xv[c];
            if (v > m) { m = v; am = c; }
        }
        int diff = am - curr;
        sh_cst  = (diff == 0) ? 1.0f : 0.0f;
        sh_incr = (diff >  0) ? 1.0f : 0.0f;
    }
    __syncthreads();
    const float cst = sh_cst;
    const float incr = sh_incr;

    float l[8];
    if (n == 0 || n == 5 || n == 10) {
#pragma unroll
        for (int c = 0; c < 8; c++) l[c] = Wv[c] + ((c < curr) ? -100.0f : 1.0f);
    } else if (n == 7) {
        const int thr = curr + 1;
        const bool inc = (incr > 0.5f);
#pragma unroll
        for (int c = 0; c < 8; c++)
            l[c] = Wv[c] + ((inc && c < thr) ? -100.0f : 1.0f);
    } else {
#pragma unroll
        for (int c = 0; c < 8; c++) l[c] = Wv[c];
    }

    float xt[8];
    gs8(l, g, xt);

    float p2 = probs;
    if (n == 7) {
        float pc = probs * (1.0f - cst);
        pc = pc + incr;
        p2 = fminf(fmaxf(pc, 0.0f), 1.0f);
    }

    float4 oa, ob;
    float* op = &oa.x;
#pragma unroll
    for (int c = 0; c < 4; c++) op[c] = p2 * xt[c] + (1.0f - p2) * xv[c];
    op = &ob.x;
#pragma unroll
    for (int c = 0; c < 4; c++) op[c] = p2 * xt[c + 4] + (1.0f - p2) * xv[c + 4];
    *reinterpret_cast<float4*>(xcf + base) = oa;
    *reinterpret_cast<float4*>(xcf + base + 4) = ob;
}

// ---------------------------------------------------------------------------
// Launch
// ---------------------------------------------------------------------------
extern "C" void kernel_launch(void* const* d_in, const int* in_sizes, int n_in,
                              void* d_out, int out_size) {
    const float* x     = (const float*)d_in[0];
    const float* truth = (const float*)d_in[1];
    const float* sw1   = (const float*)d_in[2];
    const float* sb1   = (const float*)d_in[3];
    const float* sw2   = (const float*)d_in[4];
    const float* sb2   = (const float*)d_in[5];
    const float* pw1   = (const float*)d_in[6];
    const float* pb1   = (const float*)d_in[7];
    const float* pw2   = (const float*)d_in[8];
    const float* pb2   = (const float*)d_in[9];
    const float* pw3   = (const float*)d_in[10];
    const float* pb3   = (const float*)d_in[11];
    const float* pw4   = (const float*)d_in[12];
    const float* pb4   = (const float*)d_in[13];

    float* out       = (float*)d_out;
    float* out_truth = out;
    float* out_xcf   = out + BD_ELEMS;
    float* out_P     = out + 2 * (size_t)BD_ELEMS;
    float* out_W     = out + 2 * (size_t)BD_ELEMS + BN_ELEMS;

    __half *a_hi, *a_lo, *b_hi, *b_lo, *xh, *wt_hi, *wt_lo;
    float *s1, *bias_l1;
    cudaGetSymbolAddress((void**)&a_hi, g_a_hi);
    cudaGetSymbolAddress((void**)&a_lo, g_a_lo);
    cudaGetSymbolAddress((void**)&b_hi, g_b_hi);
    cudaGetSymbolAddress((void**)&b_lo, g_b_lo);
    cudaGetSymbolAddress((void**)&xh,   g_xh);
    cudaGetSymbolAddress((void**)&s1,   g_s1);
    cudaGetSymbolAddress((void**)&wt_hi, g_wt_hi);
    cudaGetSymbolAddress((void**)&wt_lo, g_wt_lo);
    cudaGetSymbolAddress((void**)&bias_l1, g_bias_l1);

    cudaFuncSetAttribute(gemm_h<true, 2>,
                         cudaFuncAttributeMaxDynamicSharedMemorySize, GEMM_SMEM);
    cudaFuncSetAttribute(gemm_h<false, 0>,
                         cudaFuncAttributeMaxDynamicSharedMemorySize, GEMM_SMEM);
    cudaFuncSetAttribute(gemm_h<false, 1>,
                         cudaFuncAttributeMaxDynamicSharedMemorySize, GEMM_SMEM);
    cudaFuncSetAttribute(gemm2_head_kernel,
                         cudaFuncAttributeMaxDynamicSharedMemorySize, GEMM_SMEM);

    // Prep: x->fp16 + bias concat + all weight splits, one launch
    prep_kernel<<<5376, 256>>>(x, xh, pb1, sb1, bias_l1,
                               pw1, sw1, pw2, pw3, pw4, wt_hi, wt_lo);

    // L1 (pw1 + sw1 merged, AEX, mixed epilogue)
    gemm_h<true, 2><<<dim3((HP + HS) / 64, BB / 128), 256, GEMM_SMEM>>>(
        xh, nullptr, wt_hi, wt_lo, bias_l1, a_hi, a_lo, s1, DD, HP);

    // gemm2 FUSED with selector head (head fills tail waves)
    gemm2_head_kernel<<<dim3(HP / 64, BB / 128 + 16), 256, GEMM_SMEM>>>(
        a_hi, a_lo, wt_hi + OF_PW2, wt_lo + OF_PW2, pb2, b_hi, b_lo,
        s1, sw2, sb2, out_P);

    // gemm3, gemm4
    gemm_h<false, 0><<<dim3(HP / 64, BB / 128), 256, GEMM_SMEM>>>(
        b_hi, b_lo, wt_hi + OF_PW3, wt_lo + OF_PW3, pb3, a_hi, a_lo, nullptr,
        HP, HP);
    gemm_h<false, 1><<<dim3(DD / 64, BB / 128), 256, GEMM_SMEM>>>(
        a_hi, a_lo, wt_hi + OF_PW4, wt_lo + OF_PW4, pb4, nullptr, nullptr,
        out_W, HP, DD);

    // Fused tail (+ truth passthrough)
    finalize_kernel<<<BB, NN>>>(x, out_P, out_W, truth, out_truth, out_xcf);
}

// round 14
// speedup vs baseline: 1.0144x; 1.0144x over previous
#include <cuda_runtime.h>
#include <cuda_fp16.h>
#include <cstdint>
#include <math.h>

// ---------------------------------------------------------------------------
// Problem constants
// ---------------------------------------------------------------------------
#define BB 8192
#define NN 64
#define CC 8
#define DD (NN * CC)        // 512
#define HP 1024
#define HS 512
#define BD_ELEMS (BB * DD)  // 4,194,304
#define BN_ELEMS (BB * NN)  // 524,288

// ---------------------------------------------------------------------------
// Scratch (allocation-free: __device__ globals)
// ---------------------------------------------------------------------------
__device__ __half g_a_hi[BB * HP];
__device__ __half g_a_lo[BB * HP];
__device__ __half g_b_hi[BB * HP];
__device__ __half g_b_lo[BB * HP];
__device__ __half g_xh[BB * DD];
__device__ float  g_s1[BB * HS];
__device__ float  g_bias_l1[HP + HS];   // pb1 ++ sb1

// Transposed + split weights, packed (Bt[n][k] layout), fp16 hi/lo.
#define OF_PW1 0
#define OF_SW1 524288
#define OF_PW2 786432
#define OF_PW3 1835008
#define OF_PW4 2883584
#define WT_TOTAL 3407872
__device__ __half g_wt_hi[WT_TOTAL];
__device__ __half g_wt_lo[WT_TOTAL];

// ---------------------------------------------------------------------------
// Threefry-2x32-20 (JAX)
// ---------------------------------------------------------------------------
struct TFK { unsigned a, b; };

__host__ __device__ constexpr unsigned tf_rotl(unsigned v, int r) {
    return (v << r) | (v >> (32 - r));
}

__host__ __device__ constexpr TFK tf2x32(unsigned k0, unsigned k1,
                                         unsigned x0, unsigned x1) {
    unsigned k2 = k0 ^ k1 ^ 0x1BD11BDAu;
    x0 += k0; x1 += k1;
    x0 += x1; x1 = tf_rotl(x1, 13); x1 ^= x0;
    x0 += x1; x1 = tf_rotl(x1, 15); x1 ^= x0;
    x0 += x1; x1 = tf_rotl(x1, 26); x1 ^= x0;
    x0 += x1; x1 = tf_rotl(x1,  6); x1 ^= x0;
    x0 += k1; x1 += k2 + 1u;
    x0 += x1; x1 = tf_rotl(x1, 17); x1 ^= x0;
    x0 += x1; x1 = tf_rotl(x1, 29); x1 ^= x0;
    x0 += x1; x1 = tf_rotl(x1, 16); x1 ^= x0;
    x0 += x1; x1 = tf_rotl(x1, 24); x1 ^= x0;
    x0 += k2; x1 += k0 + 2u;
    x0 += x1; x1 = tf_rotl(x1, 13); x1 ^= x0;
    x0 += x1; x1 = tf_rotl(x1, 15); x1 ^= x0;
    x0 += x1; x1 = tf_rotl(x1, 26); x1 ^= x0;
    x0 += x1; x1 = tf_rotl(x1,  6); x1 ^= x0;
    x0 += k0; x1 += k1 + 3u;
    x0 += x1; x1 = tf_rotl(x1, 17); x1 ^= x0;
    x0 += x1; x1 = tf_rotl(x1, 29); x1 ^= x0;
    x0 += x1; x1 = tf_rotl(x1, 16); x1 ^= x0;
    x0 += x1; x1 = tf_rotl(x1, 24); x1 ^= x0;
    x0 += k1; x1 += k2 + 4u;
    x0 += x1; x1 = tf_rotl(x1, 13); x1 ^= x0;
    x0 += x1; x1 = tf_rotl(x1, 15); x1 ^= x0;
    x0 += x1; x1 = tf_rotl(x1, 26); x1 ^= x0;
    x0 += x1; x1 = tf_rotl(x1,  6); x1 ^= x0;
    x0 += k2; x1 += k0 + 5u;
    return TFK{x0, x1};
}

constexpr unsigned KA0 = tf2x32(0u, 42u, 0u, 0u).a;
constexpr unsigned KA1 = tf2x32(0u, 42u, 0u, 0u).b;
constexpr unsigned KB0 = tf2x32(0u, 42u, 0u, 1u).a;
constexpr unsigned KB1 = tf2x32(0u, 42u, 0u, 1u).b;
constexpr unsigned KG0 = tf2x32(0u, 42u, 0u, 2u).a;
constexpr unsigned KG1 = tf2x32(0u, 42u, 0u, 2u).b;

__device__ __forceinline__ float jax_u01(unsigned k0, unsigned k1, unsigned idx) {
    TFK r = tf2x32(k0, k1, 0u, idx);
    unsigned bits = r.a ^ r.b;
    float f = __uint_as_float((bits >> 9) | 0x3f800000u) - 1.0f;
    f = f + 1e-8f;
    return fmaxf(1e-8f, f);
}

// ---------------------------------------------------------------------------
// Helpers
// ---------------------------------------------------------------------------
__device__ __forceinline__ uint32_t smem_u32(const void* p) {
    uint32_t a;
    asm("{ .reg .u64 t; cvta.to.shared.u64 t, %1; cvt.u32.u64 %0, t; }"
        : "=r"(a) : "l"(p));
    return a;
}

#define CP16(dst_u32, src_ptr) \
    asm volatile("cp.async.cg.shared.global [%0], [%1], 16;" \
                 :: "r"(dst_u32), "l"(src_ptr) : "memory")
#define CP_COMMIT() asm volatile("cp.async.commit_group;" ::: "memory")
#define CP_WAIT(n)  asm volatile("cp.async.wait_group %0;" :: "n"(n) : "memory")

__device__ __forceinline__ void mma16(float* d, const uint32_t* a,
                                      const uint32_t* b) {
    asm volatile(
        "mma.sync.aligned.m16n8k16.row.col.f32.f16.f16.f32 "
        "{%0,%1,%2,%3}, {%4,%5,%6,%7}, {%8,%9}, {%0,%1,%2,%3};"
        : "+f"(d[0]), "+f"(d[1]), "+f"(d[2]), "+f"(d[3])
        : "r"(a[0]), "r"(a[1]), "r"(a[2]), "r"(a[3]), "r"(b[0]), "r"(b[1]));
}

__device__ __forceinline__ void ldsm_x4(uint32_t* r, uint32_t addr) {
    asm volatile(
        "ldmatrix.sync.aligned.m8n8.x4.shared.b16 {%0,%1,%2,%3}, [%4];"
        : "=r"(r[0]), "=r"(r[1]), "=r"(r[2]), "=r"(r[3]) : "r"(addr));
}

__device__ __forceinline__ void split_h(float y, __half& h, __half& l) {
    h = __float2half_rn(y);
    l = __float2half_rn(y - __half2float(h));
}

// ---------------------------------------------------------------------------
// fp16-split GEMM mainloop. BM=64, BN=128, BK=32, 256 thr, warps 2x4,
// warp tile 32x32 (acc=32 regs -> 3 CTAs/SM, LDSM/MMA=0.33).
// Packed 64B rows + XOR swizzle, 3 stages, one barrier/chunk, prefetch 2.
// ---------------------------------------------------------------------------
#define TILE_AT 4096                    // 64 rows x 64 bytes
#define TILE_BT 8192                    // 128 rows x 64 bytes
#define T_AH 0
#define T_AL TILE_AT
#define T_BH (2 * TILE_AT)
#define T_BL (2 * TILE_AT + TILE_BT)
#define STAGE_B (2 * TILE_AT + 2 * TILE_BT)  // 24576 bytes / stage
#define GEMM_SMEM (3 * STAGE_B)              // 73728 bytes

template <bool AEX>
__device__ __forceinline__ void issue_chunk_h(
    uint32_t smb, int c,
    const __half* __restrict__ A_hi, const __half* __restrict__ A_lo,
    const __half* __restrict__ B_hi, const __half* __restrict__ B_lo,
    int K, int bm0, int bn0, int tid) {
    const int k0 = c * 32;
    const uint32_t sb = smb + (uint32_t)((c % 3) * STAGE_B);
    // A: 64 rows x 4 units -> one unit per thread (hi, + lo unless AEX)
    {
        const int row = tid >> 2;
        const int q = tid & 3;
        const uint32_t doff =
            (uint32_t)(row * 64 + ((q ^ ((row >> 1) & 3)) * 16));
        CP16(sb + T_AH + doff, A_hi + (size_t)(bm0 + row) * K + k0 + q * 8);
        if (!AEX)
            CP16(sb + T_AL + doff,
                 A_lo + (size_t)(bm0 + row) * K + k0 + q * 8);
    }
    // B: 128 rows x 4 units -> two units per thread, each of hi/lo
#pragma unroll
    for (int i = 0; i < 2; i++) {
        const int f = tid + i * 256;
        const int row = f >> 2;
        const int q = f & 3;
        const uint32_t doff =
            (uint32_t)(row * 64 + ((q ^ ((row >> 1) & 3)) * 16));
        CP16(sb + T_BH + doff, B_hi + (size_t)(bn0 + row) * K + k0 + q * 8);
        CP16(sb + T_BL + doff, B_lo + (size_t)(bn0 + row) * K + k0 + q * 8);
    }
    CP_COMMIT();
}

template <bool AEX>
__device__ __forceinline__ void gemm_mainloop(
    uint32_t smb, const __half* __restrict__ A_hi,
    const __half* __restrict__ A_lo, const __half* __restrict__ Bt_hi,
    const __half* __restrict__ Bt_lo, int K, int bm0, int bn0, int tid,
    float acc[2][4][4]) {
    const int l = tid & 31;
    const int warp = tid >> 5;
    const int wm = warp >> 2;          // 0..1   (32 rows each)
    const int wn = warp & 3;           // 0..3   (32 cols each)
    const int NC = K >> 5;

    issue_chunk_h<AEX>(smb, 0, A_hi, A_lo, Bt_hi, Bt_lo, K, bm0, bn0, tid);
    if (NC > 1)
        issue_chunk_h<AEX>(smb, 1, A_hi, A_lo, Bt_hi, Bt_lo, K, bm0, bn0, tid);

    const int swz = (l >> 1) & 3;
    const uint32_t arow = (uint32_t)((wm * 32 + (l & 15)) * 64);
    const int acb = l >> 4;            // 0 or 1
    const uint32_t brow =
        (uint32_t)((wn * 32 + ((l >> 4) & 1) * 8 + (l & 7)) * 64);
    const int bcb = (l >> 3) & 1;

    for (int c = 0; c < NC; c++) {
        if (c + 1 < NC) {
            CP_WAIT(1);
        } else {
            CP_WAIT(0);
        }
        __syncthreads();
        if (c + 2 < NC)
            issue_chunk_h<AEX>(smb, c + 2, A_hi, A_lo, Bt_hi, Bt_lo, K, bm0,
                               bn0, tid);

        const uint32_t stage = smb + (uint32_t)((c % 3) * STAGE_B);
        const uint32_t baseAh = stage + T_AH + arow;
        const uint32_t baseAl = stage + T_AL + arow;
        const uint32_t baseBh = stage + T_BH + brow;
        const uint32_t baseBl = stage + T_BL + brow;

#pragma unroll
        for (int ks = 0; ks < 2; ks++) {
            const uint32_t aco = (uint32_t)(((ks * 2 + acb) ^ swz) * 16);
            const uint32_t bco = (uint32_t)(((ks * 2 + bcb) ^ swz) * 16);
            uint32_t bh[4][2], bl[4][2];
#pragma unroll
            for (int j = 0; j < 2; j++) {
                uint32_t t[4];
                ldsm_x4(t, baseBh + (uint32_t)(j * 16 * 64) + bco);
                bh[2 * j][0] = t[0]; bh[2 * j][1] = t[1];
                bh[2 * j + 1][0] = t[2]; bh[2 * j + 1][1] = t[3];
                ldsm_x4(t, baseBl + (uint32_t)(j * 16 * 64) + bco);
                bl[2 * j][0] = t[0]; bl[2 * j][1] = t[1];
                bl[2 * j + 1][0] = t[2]; bl[2 * j + 1][1] = t[3];
            }
#pragma unroll
            for (int mf = 0; mf < 2; mf++) {
                uint32_t ah[4], al[4];
                ldsm_x4(ah, baseAh + (uint32_t)(mf * 16 * 64) + aco);
                if (!AEX)
                    ldsm_x4(al, baseAl + (uint32_t)(mf * 16 * 64) + aco);
#pragma unroll
                for (int nf = 0; nf < 4; nf++) {
                    mma16(acc[mf][nf], ah, bh[nf]);
                    mma16(acc[mf][nf], ah, bl[nf]);
                    if (!AEX) mma16(acc[mf][nf], al, bh[nf]);
                }
            }
        }
    }
    __syncthreads();
}

// Epilogue for relu+split / fp32 outputs
template <int OMODE>   // 0 = relu+split, 1 = fp32, 2 = mixed L1
__device__ __forceinline__ void gemm_epilogue(
    float acc[2][4][4], const float* __restrict__ bias,
    __half* __restrict__ O_hi, __half* __restrict__ O_lo,
    float* __restrict__ Of, int Nout, int bm0, int bn0, int tid) {
    const int l = tid & 31;
    const int warp = tid >> 5;
    const int wm = warp >> 2;
    const int wn = warp & 3;
    const int rA = l >> 2;
    const int cK = l & 3;
    const bool f32_region = (OMODE == 1) || (OMODE == 2 && bn0 >= HP);
    const int ow = (OMODE == 2) ? (f32_region ? HS : HP) : Nout;
    const int cbase = (OMODE == 2 && f32_region) ? (bn0 - HP) : bn0;

#pragma unroll
    for (int nf = 0; nf < 4; nf++) {
        const int gcol = bn0 + wn * 32 + nf * 8 + 2 * cK;
        const int col = cbase + wn * 32 + nf * 8 + 2 * cK;
        const float2 bv = *reinterpret_cast<const float2*>(bias + gcol);
#pragma unroll
        for (int mf = 0; mf < 2; mf++) {
            const int ra = bm0 + wm * 32 + mf * 16 + rA;
            float y[4];
            y[0] = acc[mf][nf][0] + bv.x;
            y[1] = acc[mf][nf][1] + bv.y;
            y[2] = acc[mf][nf][2] + bv.x;
            y[3] = acc[mf][nf][3] + bv.y;
            if (OMODE != 1) {
#pragma unroll
                for (int r = 0; r < 4; r++) y[r] = fmaxf(y[r], 0.0f);
            }
            if (!f32_region && OMODE != 1) {
                __half h[4], lo[4];
#pragma unroll
                for (int r = 0; r < 4; r++) split_h(y[r], h[r], lo[r]);
                *reinterpret_cast<__half2*>(O_hi + (size_t)ra * ow + col) =
                    __halves2half2(h[0], h[1]);
                *reinterpret_cast<__half2*>(O_hi + (size_t)(ra + 8) * ow + col) =
                    __halves2half2(h[2], h[3]);
                *reinterpret_cast<__half2*>(O_lo + (size_t)ra * ow + col) =
                    __halves2half2(lo[0], lo[1]);
                *reinterpret_cast<__half2*>(O_lo + (size_t)(ra + 8) * ow + col) =
                    __halves2half2(lo[2], lo[3]);
            } else {
                *reinterpret_cast<float2*>(Of + (size_t)ra * ow + col) =
                    make_float2(y[0], y[1]);
                *reinterpret_cast<float2*>(Of + (size_t)(ra + 8) * ow + col) =
                    make_float2(y[2], y[3]);
            }
        }
    }
}

// Plain GEMM kernels (L1 mixed, L3 split, L4 fp32)
template <bool AEX, int OMODE>
__global__ void __launch_bounds__(256, 3)
gemm_h(const __half* __restrict__ A_hi, const __half* __restrict__ A_lo,
       const __half* __restrict__ Bt_hi, const __half* __restrict__ Bt_lo,
       const float* __restrict__ bias,
       __half* __restrict__ O_hi, __half* __restrict__ O_lo,
       float* __restrict__ Of,
       int K, int Nout) {
    extern __shared__ __half smh[];
    const uint32_t smb = smem_u32(smh);
    const int tid = threadIdx.x;
    const int bm0 = blockIdx.y * 64;
    const int bn0 = blockIdx.x * 128;

    float acc[2][4][4];
#pragma unroll
    for (int mf = 0; mf < 2; mf++)
#pragma unroll
        for (int nf = 0; nf < 4; nf++)
#pragma unroll
            for (int r = 0; r < 4; r++) acc[mf][nf][r] = 0.0f;

    gemm_mainloop<AEX>(smb, A_hi, A_lo, Bt_hi, Bt_lo, K, bm0, bn0, tid, acc);
    gemm_epilogue<OMODE>(acc, bias, O_hi, O_lo, Of, Nout, bm0, bn0, tid);
}

// ---------------------------------------------------------------------------
// Selector head body (3-stage cp.async pipeline) — runs inside fused kernel.
// ---------------------------------------------------------------------------
__device__ __forceinline__ void sel_head_body(
    char* smc, int bm0, int tid,
    const float* __restrict__ A, const float* __restrict__ B,
    const float* __restrict__ bias, float* __restrict__ C) {
    float (*As)[32][20] = reinterpret_cast<float (*)[32][20]>(smc);
    float (*Bs)[16][64] = reinterpret_cast<float (*)[16][64]>(smc + 3 * 32 * 20 * 4);

    const int tx = tid & 15;
    const int ty = tid >> 4;
    const int K = HS, N = NN;
    const int NC = K / 16;

    const uint32_t asb = smem_u32(As);
    const uint32_t bsb = smem_u32(Bs);

    auto issue = [&](int c) {
        const int s = c % 3;
        const int k0 = c * 16;
        if (tid < 128) {
            const int row = tid >> 2;
            const int q = tid & 3;
            CP16(asb + (uint32_t)(((s * 32 + row) * 20 + q * 4) * 4),
                 A + (size_t)(bm0 + row) * K + k0 + q * 4);
        }
        {
            const int kr = tid >> 4;
            const int q = tid & 15;
            CP16(bsb + (uint32_t)(((s * 16 + kr) * 64 + q * 4) * 4),
                 B + (size_t)(k0 + kr) * N + q * 4);
        }
        CP_COMMIT();
    };

    float acc[2][4] = {{0.f, 0.f, 0.f, 0.f}, {0.f, 0.f, 0.f, 0.f}};

    issue(0);
    issue(1);

    for (int c = 0; c < NC; c++) {
        const int s = c % 3;
        if (c + 1 < NC) CP_WAIT(1); else CP_WAIT(0);
        __syncthreads();
        if (c + 2 < NC) issue(c + 2);

#pragma unroll
        for (int k = 0; k < 16; k++) {
            float a0 = As[s][ty * 2][k];
            float a1 = As[s][ty * 2 + 1][k];
            float4 bv = *reinterpret_cast<const float4*>(&Bs[s][k][tx * 4]);
            acc[0][0] = fmaf(a0, bv.x, acc[0][0]);
            acc[0][1] = fmaf(a0, bv.y, acc[0][1]);
            acc[0][2] = fmaf(a0, bv.z, acc[0][2]);
            acc[0][3] = fmaf(a0, bv.w, acc[0][3]);
            acc[1][0] = fmaf(a1, bv.x, acc[1][0]);
            acc[1][1] = fmaf(a1, bv.y, acc[1][1]);
            acc[1][2] = fmaf(a1, bv.z, acc[1][2]);
            acc[1][3] = fmaf(a1, bv.w, acc[1][3]);
        }
    }

    float4 bvec = *reinterpret_cast<const float4*>(bias + tx * 4);
    float bias4[4] = {bvec.x, bvec.y, bvec.z, bvec.w};
#pragma unroll
    for (int i = 0; i < 2; i++) {
        float4 v;
        float* vp = &v.x;
#pragma unroll
        for (int j = 0; j < 4; j++) {
            float cv = acc[i][j] + bias4[j];
            vp[j] = 1.0f / (1.0f + expf(-cv));
        }
        *reinterpret_cast<float4*>(
            C + (size_t)(bm0 + ty * 2 + i) * N + tx * 4) = v;
    }
}

// ---------------------------------------------------------------------------
// FUSED gemm2 + selector head. grid = (8, 128 + 32):
//   y <  128: gemm2 tile; y >= 128: head block hb = (y-128)*8 + x in [0,256)
// ---------------------------------------------------------------------------
__global__ void __launch_bounds__(256, 3)
gemm2_head_kernel(const __half* __restrict__ A_hi,
                  const __half* __restrict__ A_lo,
                  const __half* __restrict__ Bt_hi,
                  const __half* __restrict__ Bt_lo,
                  const float* __restrict__ bias,
                  __half* __restrict__ O_hi, __half* __restrict__ O_lo,
                  const float* __restrict__ s1, const float* __restrict__ sw2,
                  const float* __restrict__ sb2, float* __restrict__ P) {
    extern __shared__ char smc[];
    const int tid = threadIdx.x;

    if (blockIdx.y >= 128) {
        const int hb = (blockIdx.y - 128) * 8 + blockIdx.x;   // 0..255
        sel_head_body(smc, hb * 32, tid, s1, sw2, sb2, P);
        return;
    }

    const uint32_t smb = smem_u32(smc);
    const int bm0 = blockIdx.y * 64;
    const int bn0 = blockIdx.x * 128;

    float acc[2][4][4];
#pragma unroll
    for (int mf = 0; mf < 2; mf++)
#pragma unroll
        for (int nf = 0; nf < 4; nf++)
#pragma unroll
            for (int r = 0; r < 4; r++) acc[mf][nf][r] = 0.0f;

    gemm_mainloop<false>(smb, A_hi, A_lo, Bt_hi, Bt_lo, HP, bm0, bn0, tid, acc);
    gemm_epilogue<0>(acc, bias, O_hi, O_lo, nullptr, HP, bm0, bn0, tid);
}

// ---------------------------------------------------------------------------
// MERGED prep kernel
// ---------------------------------------------------------------------------
__global__ void __launch_bounds__(256)
prep_kernel(const float* __restrict__ x, __half* __restrict__ xh,
            const float* __restrict__ pb1, const float* __restrict__ sb1,
            float* __restrict__ bias_l1,
            const float* __restrict__ pw1, const float* __restrict__ sw1,
            const float* __restrict__ pw2, const float* __restrict__ pw3,
            const float* __restrict__ pw4,
            __half* __restrict__ bt_hi, __half* __restrict__ bt_lo) {
    if (blockIdx.x < 2048) {
        const int t = blockIdx.x * 256 + threadIdx.x;
        const float4 a = *reinterpret_cast<const float4*>(x + (size_t)t * 8);
        const float4 b = *reinterpret_cast<const float4*>(x + (size_t)t * 8 + 4);
        __half2 o[4];
        o[0] = __halves2half2(__float2half_rn(a.x), __float2half_rn(a.y));
        o[1] = __halves2half2(__float2half_rn(a.z), __float2half_rn(a.w));
        o[2] = __halves2half2(__float2half_rn(b.x), __float2half_rn(b.y));
        o[3] = __halves2half2(__float2half_rn(b.z), __float2half_rn(b.w));
        *reinterpret_cast<uint4*>(xh + (size_t)t * 8) =
            *reinterpret_cast<uint4*>(o);
        if (t < HP + HS)
            bias_l1[t] = (t < HP) ? pb1[t] : sb1[t - HP];
        return;
    }

    const int b = blockIdx.x - 2048;
    const float* W;
    int off, K, N, lb;
    if (b < 512)        { W = pw1; off = OF_PW1; K = 512;  N = 1024; lb = b; }
    else if (b < 768)   { W = sw1; off = OF_SW1; K = 512;  N = 512;  lb = b - 512; }
    else if (b < 1792)  { W = pw2; off = OF_PW2; K = 1024; N = 1024; lb = b - 768; }
    else if (b < 2816)  { W = pw3; off = OF_PW3; K = 1024; N = 1024; lb = b - 1792; }
    else                { W = pw4; off = OF_PW4; K = 1024; N = 512;  lb = b - 2816; }
    const int kt = K >> 5;
    const int kb = (lb % kt) * 32;
    const int nb = (lb / kt) * 32;

    __shared__ float t[32][33];
    const int tx = threadIdx.x & 31;
    const int ty = threadIdx.x >> 5;
#pragma unroll
    for (int r = ty; r < 32; r += 8)
        t[r][tx] = W[(size_t)(kb + r) * N + nb + tx];
    __syncthreads();
#pragma unroll
    for (int r = ty; r < 32; r += 8) {
        float wv = t[tx][r];
        __half h, lo;
        split_h(wv, h, lo);
        size_t o = (size_t)off + (size_t)(nb + r) * K + kb + tx;
        bt_hi[o] = h;
        bt_lo[o] = lo;
    }
}

// ---------------------------------------------------------------------------
// Fused elementwise tail (+ truth_x passthrough)
// ---------------------------------------------------------------------------
__device__ __forceinline__ void gs8(const float* l, const float* g, float* xt) {
    float m = l[0];
#pragma unroll
    for (int c = 1; c < 8; c++) m = fmaxf(m, l[c]);
    float e[8], s = 0.0f;
#pragma unroll
    for (int c = 0; c < 8; c++) { e[c] = expf(l[c] - m); s += e[c]; }
    float t[8];
#pragma unroll
    for (int c = 0; c < 8; c++) {
        float pr = e[c] / s;
        pr = 0.9f * pr + 0.0125f;
        t[c] = (logf(pr) + g[c]) / 0.7f;
    }
    float m2 = t[0];
#pragma unroll
    for (int c = 1; c < 8; c++) m2 = fmaxf(m2, t[c]);
    float e2[8], s2 = 0.0f;
#pragma unroll
    for (int c = 0; c < 8; c++) { e2[c] = expf(t[c] - m2); s2 += e2[c]; }
#pragma unroll
    for (int c = 0; c < 8; c++) xt[c] = e2[c] / s2;
}

__global__ void finalize_kernel(const float* __restrict__ x,
                                const float* __restrict__ Pm,
                                const float* __restrict__ W,
                                const float* __restrict__ truth,
                                float* __restrict__ out_truth,
                                float* __restrict__ xcf) {
    const int b = blockIdx.x;
    const int n = threadIdx.x;
    __shared__ float sh_cst, sh_incr;

    const size_t base = (size_t)b * DD + n * CC;

    *reinterpret_cast<float4*>(out_truth + base) =
        *reinterpret_cast<const float4*>(truth + base);
    *reinterpret_cast<float4*>(out_truth + base + 4) =
        *reinterpret_cast<const float4*>(truth + base + 4);

    float4 xa = *reinterpret_cast<const float4*>(x + base);
    float4 xb = *reinterpret_cast<const float4*>(x + base + 4);
    float4 wa = *reinterpret_cast<const float4*>(W + base);
    float4 wb = *reinterpret_cast<const float4*>(W + base + 4);
    float xv[8] = {xa.x, xa.y, xa.z, xa.w, xb.x, xb.y, xb.z, xb.w};
    float Wv[8] = {wa.x, wa.y, wa.z, wa.w, wb.x, wb.y, wb.z, wb.w};

    const unsigned i = (unsigned)(b * NN + n);
    const float P = Pm[i];

    float ua = jax_u01(KA0, KA1, i);
    float ub = jax_u01(KB0, KB1, i);
    float ea = expf(-logf(-logf(ua)));
    float eb = expf(-logf(-logf(ub)));
    float no = P * ea / 0.7f;
    float de = no + (1.0f - P) * eb / 0.7f;
    float probs = no / de;

    float g[8];
#pragma unroll
    for (int c = 0; c < 8; c++) {
        float u = jax_u01(KG0, KG1, i * 8u + (unsigned)c);
        g[c] = -logf(-logf(u));
    }

    int curr = 0;
    {
        float m = xv[0];
#pragma unroll
        for (int c = 1; c < 8; c++)
            if (xv[c] > m) { m = xv[c]; curr = c; }
    }

    if (n == 2) {
        float xt_par[8];
        gs8(Wv, g, xt_par);
        int am = 0;
        float m = probs * xt_par[0] + (1.0f - probs) * xv[0];
#pragma unroll
        for (int c = 1; c < 8; c++) {
            float v = probs * xt_par[c] + (1.0f - probs) * xv[c];
            if (v > m) { m = v; am = c; }
        }
        int diff = am - curr;
        sh_cst  = (diff == 0) ? 1.0f : 0.0f;
        sh_incr = (diff >  0) ? 1.0f : 0.0f;
    }
    __syncthreads();
    const float cst = sh_cst;
    const float incr = sh_incr;

    float l[8];
    if (n == 0 || n == 5 || n == 10) {
#pragma unroll
        for (int c = 0; c < 8; c++) l[c] = Wv[c] + ((c < curr) ? -100.0f : 1.0f);
    } else if (n == 7) {
        const int thr = curr + 1;
        const bool inc = (incr > 0.5f);
#pragma unroll
        for (int c = 0; c < 8; c++)
            l[c] = Wv[c] + ((inc && c < thr) ? -100.0f : 1.0f);
    } else {
#pragma unroll
        for (int c = 0; c < 8; c++) l[c] = Wv[c];
    }

    float xt[8];
    gs8(l, g, xt);

    float p2 = probs;
    if (n == 7) {
        float pc = probs * (1.0f - cst);
        pc = pc + incr;
        p2 = fminf(fmaxf(pc, 0.0f), 1.0f);
    }

    float4 oa, ob;
    float* op = &oa.x;
#pragma unroll
    for (int c = 0; c < 4; c++) op[c] = p2 * xt[c] + (1.0f - p2) * xv[c];
    op = &ob.x;
#pragma unroll
    for (int c = 0; c < 4; c++) op[c] = p2 * xt[c + 4] + (1.0f - p2) * xv[c + 4];
    *reinterpret_cast<float4*>(xcf + base) = oa;
    *reinterpret_cast<float4*>(xcf + base + 4) = ob;
}

// ---------------------------------------------------------------------------
// Launch
// ---------------------------------------------------------------------------
extern "C" void kernel_launch(void* const* d_in, const int* in_sizes, int n_in,
                              void* d_out, int out_size) {
    const float* x     = (const float*)d_in[0];
    const float* truth = (const float*)d_in[1];
    const float* sw1   = (const float*)d_in[2];
    const float* sb1   = (const float*)d_in[3];
    const float* sw2   = (const float*)d_in[4];
    const float* sb2   = (const float*)d_in[5];
    const float* pw1   = (const float*)d_in[6];
    const float* pb1   = (const float*)d_in[7];
    const float* pw2   = (const float*)d_in[8];
    const float* pb2   = (const float*)d_in[9];
    const float* pw3   = (const float*)d_in[10];
    const float* pb3   = (const float*)d_in[11];
    const float* pw4   = (const float*)d_in[12];
    const float* pb4   = (const float*)d_in[13];

    float* out       = (float*)d_out;
    float* out_truth = out;
    float* out_xcf   = out + BD_ELEMS;
    float* out_P     = out + 2 * (size_t)BD_ELEMS;
    float* out_W     = out + 2 * (size_t)BD_ELEMS + BN_ELEMS;

    __half *a_hi, *a_lo, *b_hi, *b_lo, *xh, *wt_hi, *wt_lo;
    float *s1, *bias_l1;
    cudaGetSymbolAddress((void**)&a_hi, g_a_hi);
    cudaGetSymbolAddress((void**)&a_lo, g_a_lo);
    cudaGetSymbolAddress((void**)&b_hi, g_b_hi);
    cudaGetSymbolAddress((void**)&b_lo, g_b_lo);
    cudaGetSymbolAddress((void**)&xh,   g_xh);
    cudaGetSymbolAddress((void**)&s1,   g_s1);
    cudaGetSymbolAddress((void**)&wt_hi, g_wt_hi);
    cudaGetSymbolAddress((void**)&wt_lo, g_wt_lo);
    cudaGetSymbolAddress((void**)&bias_l1, g_bias_l1);

    cudaFuncSetAttribute(gemm_h<true, 2>,
                         cudaFuncAttributeMaxDynamicSharedMemorySize, GEMM_SMEM);
    cudaFuncSetAttribute(gemm_h<false, 0>,
                         cudaFuncAttributeMaxDynamicSharedMemorySize, GEMM_SMEM);
    cudaFuncSetAttribute(gemm_h<false, 1>,
                         cudaFuncAttributeMaxDynamicSharedMemorySize, GEMM_SMEM);
    cudaFuncSetAttribute(gemm2_head_kernel,
                         cudaFuncAttributeMaxDynamicSharedMemorySize, GEMM_SMEM);

    // Prep: x->fp16 + bias concat + all weight splits, one launch
    prep_kernel<<<5376, 256>>>(x, xh, pb1, sb1, bias_l1,
                               pw1, sw1, pw2, pw3, pw4, wt_hi, wt_lo);

    // L1 (pw1 + sw1 merged, AEX, mixed epilogue)
    gemm_h<true, 2><<<dim3((HP + HS) / 128, BB / 64), 256, GEMM_SMEM>>>(
        xh, nullptr, wt_hi, wt_lo, bias_l1, a_hi, a_lo, s1, DD, HP);

    // gemm2 FUSED with selector head (head fills tail waves)
    gemm2_head_kernel<<<dim3(HP / 128, BB / 64 + 32), 256, GEMM_SMEM>>>(
        a_hi, a_lo, wt_hi + OF_PW2, wt_lo + OF_PW2, pb2, b_hi, b_lo,
        s1, sw2, sb2, out_P);

    // gemm3, gemm4
    gemm_h<false, 0><<<dim3(HP / 128, BB / 64), 256, GEMM_SMEM>>>(
        b_hi, b_lo, wt_hi + OF_PW3, wt_lo + OF_PW3, pb3, a_hi, a_lo, nullptr,
        HP, HP);
    gemm_h<false, 1><<<dim3(DD / 128, BB / 64), 256, GEMM_SMEM>>>(
        a_hi, a_lo, wt_hi + OF_PW4, wt_lo + OF_PW4, pb4, nullptr, nullptr,
        out_W, HP, DD);

    // Fused tail (+ truth passthrough)
    finalize_kernel<<<BB, NN>>>(x, out_P, out_W, truth, out_truth, out_xcf);
}

// round 15
// speedup vs baseline: 1.0603x; 1.0452x over previous
#include <cuda_runtime.h>
#include <cuda_fp16.h>
#include <cstdint>
#include <math.h>

// ---------------------------------------------------------------------------
// Problem constants
// ---------------------------------------------------------------------------
#define BB 8192
#define NN 64
#define CC 8
#define DD (NN * CC)        // 512
#define HP 1024
#define HS 512
#define BD_ELEMS (BB * DD)  // 4,194,304
#define BN_ELEMS (BB * NN)  // 524,288

// ---------------------------------------------------------------------------
// Scratch (allocation-free: __device__ globals)
// ---------------------------------------------------------------------------
__device__ __half g_a_hi[BB * HP];
__device__ __half g_a_lo[BB * HP];
__device__ __half g_b_hi[BB * HP];
__device__ __half g_b_lo[BB * HP];
__device__ __half g_xh[BB * DD];
__device__ float  g_s1[BB * HS];
__device__ float  g_bias_l1[HP + HS];   // pb1 ++ sb1
__device__ float  g_ea[BN_ELEMS];
__device__ float  g_eb[BN_ELEMS];
__device__ float  g_gum[BN_ELEMS * 8];

// Transposed + split weights, packed (Bt[n][k] layout), fp16 hi/lo.
#define OF_PW1 0
#define OF_SW1 524288
#define OF_PW2 786432
#define OF_PW3 1835008
#define OF_PW4 2883584
#define WT_TOTAL 3407872
__device__ __half g_wt_hi[WT_TOTAL];
__device__ __half g_wt_lo[WT_TOTAL];

// ---------------------------------------------------------------------------
// Threefry-2x32-20 (JAX)
// ---------------------------------------------------------------------------
struct TFK { unsigned a, b; };

__host__ __device__ constexpr unsigned tf_rotl(unsigned v, int r) {
    return (v << r) | (v >> (32 - r));
}

__host__ __device__ constexpr TFK tf2x32(unsigned k0, unsigned k1,
                                         unsigned x0, unsigned x1) {
    unsigned k2 = k0 ^ k1 ^ 0x1BD11BDAu;
    x0 += k0; x1 += k1;
    x0 += x1; x1 = tf_rotl(x1, 13); x1 ^= x0;
    x0 += x1; x1 = tf_rotl(x1, 15); x1 ^= x0;
    x0 += x1; x1 = tf_rotl(x1, 26); x1 ^= x0;
    x0 += x1; x1 = tf_rotl(x1,  6); x1 ^= x0;
    x0 += k1; x1 += k2 + 1u;
    x0 += x1; x1 = tf_rotl(x1, 17); x1 ^= x0;
    x0 += x1; x1 = tf_rotl(x1, 29); x1 ^= x0;
    x0 += x1; x1 = tf_rotl(x1, 16); x1 ^= x0;
    x0 += x1; x1 = tf_rotl(x1, 24); x1 ^= x0;
    x0 += k2; x1 += k0 + 2u;
    x0 += x1; x1 = tf_rotl(x1, 13); x1 ^= x0;
    x0 += x1; x1 = tf_rotl(x1, 15); x1 ^= x0;
    x0 += x1; x1 = tf_rotl(x1, 26); x1 ^= x0;
    x0 += x1; x1 = tf_rotl(x1,  6); x1 ^= x0;
    x0 += k0; x1 += k1 + 3u;
    x0 += x1; x1 = tf_rotl(x1, 17); x1 ^= x0;
    x0 += x1; x1 = tf_rotl(x1, 29); x1 ^= x0;
    x0 += x1; x1 = tf_rotl(x1, 16); x1 ^= x0;
    x0 += x1; x1 = tf_rotl(x1, 24); x1 ^= x0;
    x0 += k1; x1 += k2 + 4u;
    x0 += x1; x1 = tf_rotl(x1, 13); x1 ^= x0;
    x0 += x1; x1 = tf_rotl(x1, 15); x1 ^= x0;
    x0 += x1; x1 = tf_rotl(x1, 26); x1 ^= x0;
    x0 += x1; x1 = tf_rotl(x1,  6); x1 ^= x0;
    x0 += k2; x1 += k0 + 5u;
    return TFK{x0, x1};
}

constexpr unsigned KA0 = tf2x32(0u, 42u, 0u, 0u).a;
constexpr unsigned KA1 = tf2x32(0u, 42u, 0u, 0u).b;
constexpr unsigned KB0 = tf2x32(0u, 42u, 0u, 1u).a;
constexpr unsigned KB1 = tf2x32(0u, 42u, 0u, 1u).b;
constexpr unsigned KG0 = tf2x32(0u, 42u, 0u, 2u).a;
constexpr unsigned KG1 = tf2x32(0u, 42u, 0u, 2u).b;

__device__ __forceinline__ float jax_u01(unsigned k0, unsigned k1, unsigned idx) {
    TFK r = tf2x32(k0, k1, 0u, idx);
    unsigned bits = r.a ^ r.b;
    float f = __uint_as_float((bits >> 9) | 0x3f800000u) - 1.0f;
    f = f + 1e-8f;
    return fmaxf(1e-8f, f);
}

// ---------------------------------------------------------------------------
// Helpers
// ---------------------------------------------------------------------------
__device__ __forceinline__ uint32_t smem_u32(const void* p) {
    uint32_t a;
    asm("{ .reg .u64 t; cvta.to.shared.u64 t, %1; cvt.u32.u64 %0, t; }"
        : "=r"(a) : "l"(p));
    return a;
}

#define CP16(dst_u32, src_ptr) \
    asm volatile("cp.async.cg.shared.global [%0], [%1], 16;" \
                 :: "r"(dst_u32), "l"(src_ptr) : "memory")
#define CP_COMMIT() asm volatile("cp.async.commit_group;" ::: "memory")
#define CP_WAIT(n)  asm volatile("cp.async.wait_group %0;" :: "n"(n) : "memory")

__device__ __forceinline__ void mma16(float* d, const uint32_t* a,
                                      const uint32_t* b) {
    asm volatile(
        "mma.sync.aligned.m16n8k16.row.col.f32.f16.f16.f32 "
        "{%0,%1,%2,%3}, {%4,%5,%6,%7}, {%8,%9}, {%0,%1,%2,%3};"
        : "+f"(d[0]), "+f"(d[1]), "+f"(d[2]), "+f"(d[3])
        : "r"(a[0]), "r"(a[1]), "r"(a[2]), "r"(a[3]), "r"(b[0]), "r"(b[1]));
}

__device__ __forceinline__ void ldsm_x4(uint32_t* r, uint32_t addr) {
    asm volatile(
        "ldmatrix.sync.aligned.m8n8.x4.shared.b16 {%0,%1,%2,%3}, [%4];"
        : "=r"(r[0]), "=r"(r[1]), "=r"(r[2]), "=r"(r[3]) : "r"(addr));
}

__device__ __forceinline__ void split_h(float y, __half& h, __half& l) {
    h = __float2half_rn(y);
    l = __float2half_rn(y - __half2float(h));
}

// ---------------------------------------------------------------------------
// fp16-split GEMM mainloop. BM=64, BN=32*NF, BK=32, 256 thr, warps 2x4,
// warp tile 32 x (8*NF). Packed 64B rows + XOR swizzle, 3 stages,
// one barrier/chunk, prefetch distance 2.
// ---------------------------------------------------------------------------
#define TILE_AT 4096                    // 64 rows x 64 bytes

template <int NF> struct TileCfg {
    static constexpr int TILE_BT = 32 * NF * 64;          // B rows x 64B
    static constexpr int T_AH = 0;
    static constexpr int T_AL = TILE_AT;
    static constexpr int T_BH = 2 * TILE_AT;
    static constexpr int T_BL = 2 * TILE_AT + TILE_BT;
    static constexpr int STAGE = 2 * TILE_AT + 2 * TILE_BT;
    static constexpr int SMEM = 3 * STAGE;
};
// NF=4: STAGE=24576, SMEM=73728.  NF=2: STAGE=16384, SMEM=49152.

template <bool AEX, int NF>
__device__ __forceinline__ void issue_chunk_h(
    uint32_t smb, int c,
    const __half* __restrict__ A_hi, const __half* __restrict__ A_lo,
    const __half* __restrict__ B_hi, const __half* __restrict__ B_lo,
    int K, int bm0, int bn0, int tid) {
    using C_ = TileCfg<NF>;
    const int k0 = c * 32;
    const uint32_t sb = smb + (uint32_t)((c % 3) * C_::STAGE);
    // A: 64 rows x 4 units -> one unit per thread (hi, + lo unless AEX)
    {
        const int row = tid >> 2;
        const int q = tid & 3;
        const uint32_t doff =
            (uint32_t)(row * 64 + ((q ^ ((row >> 1) & 3)) * 16));
        CP16(sb + C_::T_AH + doff, A_hi + (size_t)(bm0 + row) * K + k0 + q * 8);
        if (!AEX)
            CP16(sb + C_::T_AL + doff,
                 A_lo + (size_t)(bm0 + row) * K + k0 + q * 8);
    }
    // B: 32*NF rows x 4 units -> NF/2 units per thread, each of hi/lo
#pragma unroll
    for (int i = 0; i < NF / 2; i++) {
        const int f = tid + i * 256;
        const int row = f >> 2;
        const int q = f & 3;
        const uint32_t doff =
            (uint32_t)(row * 64 + ((q ^ ((row >> 1) & 3)) * 16));
        CP16(sb + C_::T_BH + doff, B_hi + (size_t)(bn0 + row) * K + k0 + q * 8);
        CP16(sb + C_::T_BL + doff, B_lo + (size_t)(bn0 + row) * K + k0 + q * 8);
    }
    CP_COMMIT();
}

template <bool AEX, int NF>
__device__ __forceinline__ void gemm_mainloop(
    uint32_t smb, const __half* __restrict__ A_hi,
    const __half* __restrict__ A_lo, const __half* __restrict__ Bt_hi,
    const __half* __restrict__ Bt_lo, int K, int bm0, int bn0, int tid,
    float acc[2][NF][4]) {
    using C_ = TileCfg<NF>;
    const int l = tid & 31;
    const int warp = tid >> 5;
    const int wm = warp >> 2;          // 0..1 (32 rows each)
    const int wn = warp & 3;           // 0..3 (8*NF cols each)
    const int NC = K >> 5;

    issue_chunk_h<AEX, NF>(smb, 0, A_hi, A_lo, Bt_hi, Bt_lo, K, bm0, bn0, tid);
    if (NC > 1)
        issue_chunk_h<AEX, NF>(smb, 1, A_hi, A_lo, Bt_hi, Bt_lo, K, bm0, bn0,
                               tid);

    const int swz = (l >> 1) & 3;
    const uint32_t arow = (uint32_t)((wm * 32 + (l & 15)) * 64);
    const int acb = l >> 4;            // 0 or 1
    const uint32_t brow =
        (uint32_t)((wn * NF * 8 + ((l >> 4) & 1) * 8 + (l & 7)) * 64);
    const int bcb = (l >> 3) & 1;

    for (int c = 0; c < NC; c++) {
        if (c + 1 < NC) {
            CP_WAIT(1);
        } else {
            CP_WAIT(0);
        }
        __syncthreads();
        if (c + 2 < NC)
            issue_chunk_h<AEX, NF>(smb, c + 2, A_hi, A_lo, Bt_hi, Bt_lo, K,
                                   bm0, bn0, tid);

        const uint32_t stage = smb + (uint32_t)((c % 3) * C_::STAGE);
        const uint32_t baseAh = stage + C_::T_AH + arow;
        const uint32_t baseAl = stage + C_::T_AL + arow;
        const uint32_t baseBh = stage + C_::T_BH + brow;
        const uint32_t baseBl = stage + C_::T_BL + brow;

#pragma unroll
        for (int ks = 0; ks < 2; ks++) {
            const uint32_t aco = (uint32_t)(((ks * 2 + acb) ^ swz) * 16);
            const uint32_t bco = (uint32_t)(((ks * 2 + bcb) ^ swz) * 16);
            uint32_t bh[NF][2], bl[NF][2];
#pragma unroll
            for (int j = 0; j < NF / 2; j++) {
                uint32_t t[4];
                ldsm_x4(t, baseBh + (uint32_t)(j * 16 * 64) + bco);
                bh[2 * j][0] = t[0]; bh[2 * j][1] = t[1];
                bh[2 * j + 1][0] = t[2]; bh[2 * j + 1][1] = t[3];
                ldsm_x4(t, baseBl + (uint32_t)(j * 16 * 64) + bco);
                bl[2 * j][0] = t[0]; bl[2 * j][1] = t[1];
                bl[2 * j + 1][0] = t[2]; bl[2 * j + 1][1] = t[3];
            }
#pragma unroll
            for (int mf = 0; mf < 2; mf++) {
                uint32_t ah[4], al[4];
                ldsm_x4(ah, baseAh + (uint32_t)(mf * 16 * 64) + aco);
                if (!AEX)
                    ldsm_x4(al, baseAl + (uint32_t)(mf * 16 * 64) + aco);
#pragma unroll
                for (int nf = 0; nf < NF; nf++) {
                    mma16(acc[mf][nf], ah, bh[nf]);
                    mma16(acc[mf][nf], ah, bl[nf]);
                    if (!AEX) mma16(acc[mf][nf], al, bh[nf]);
                }
            }
        }
    }
    __syncthreads();
}

// Epilogue for relu+split / fp32 outputs
template <int OMODE, int NF>   // OMODE: 0 = relu+split, 1 = fp32, 2 = mixed L1
__device__ __forceinline__ void gemm_epilogue(
    float acc[2][NF][4], const float* __restrict__ bias,
    __half* __restrict__ O_hi, __half* __restrict__ O_lo,
    float* __restrict__ Of, int Nout, int bm0, int bn0, int tid) {
    const int l = tid & 31;
    const int warp = tid >> 5;
    const int wm = warp >> 2;
    const int wn = warp & 3;
    const int rA = l >> 2;
    const int cK = l & 3;
    const bool f32_region = (OMODE == 1) || (OMODE == 2 && bn0 >= HP);
    const int ow = (OMODE == 2) ? (f32_region ? HS : HP) : Nout;
    const int cbase = (OMODE == 2 && f32_region) ? (bn0 - HP) : bn0;

#pragma unroll
    for (int nf = 0; nf < NF; nf++) {
        const int gcol = bn0 + wn * NF * 8 + nf * 8 + 2 * cK;
        const int col = cbase + wn * NF * 8 + nf * 8 + 2 * cK;
        const float2 bv = *reinterpret_cast<const float2*>(bias + gcol);
#pragma unroll
        for (int mf = 0; mf < 2; mf++) {
            const int ra = bm0 + wm * 32 + mf * 16 + rA;
            float y[4];
            y[0] = acc[mf][nf][0] + bv.x;
            y[1] = acc[mf][nf][1] + bv.y;
            y[2] = acc[mf][nf][2] + bv.x;
            y[3] = acc[mf][nf][3] + bv.y;
            if (OMODE != 1) {
#pragma unroll
                for (int r = 0; r < 4; r++) y[r] = fmaxf(y[r], 0.0f);
            }
            if (!f32_region && OMODE != 1) {
                __half h[4], lo[4];
#pragma unroll
                for (int r = 0; r < 4; r++) split_h(y[r], h[r], lo[r]);
                *reinterpret_cast<__half2*>(O_hi + (size_t)ra * ow + col) =
                    __halves2half2(h[0], h[1]);
                *reinterpret_cast<__half2*>(O_hi + (size_t)(ra + 8) * ow + col) =
                    __halves2half2(h[2], h[3]);
                *reinterpret_cast<__half2*>(O_lo + (size_t)ra * ow + col) =
                    __halves2half2(lo[0], lo[1]);
                *reinterpret_cast<__half2*>(O_lo + (size_t)(ra + 8) * ow + col) =
                    __halves2half2(lo[2], lo[3]);
            } else {
                *reinterpret_cast<float2*>(Of + (size_t)ra * ow + col) =
                    make_float2(y[0], y[1]);
                *reinterpret_cast<float2*>(Of + (size_t)(ra + 8) * ow + col) =
                    make_float2(y[2], y[3]);
            }
        }
    }
}

// Plain GEMM kernels (L1 mixed NF=4, L3 split NF=4, L4 fp32 NF=2)
template <bool AEX, int OMODE, int NF>
__global__ void __launch_bounds__(256, 3)
gemm_h(const __half* __restrict__ A_hi, const __half* __restrict__ A_lo,
       const __half* __restrict__ Bt_hi, const __half* __restrict__ Bt_lo,
       const float* __restrict__ bias,
       __half* __restrict__ O_hi, __half* __restrict__ O_lo,
       float* __restrict__ Of,
       int K, int Nout) {
    extern __shared__ __half smh[];
    const uint32_t smb = smem_u32(smh);
    const int tid = threadIdx.x;
    const int bm0 = blockIdx.y * 64;
    const int bn0 = blockIdx.x * (NF * 32);

    float acc[2][NF][4];
#pragma unroll
    for (int mf = 0; mf < 2; mf++)
#pragma unroll
        for (int nf = 0; nf < NF; nf++)
#pragma unroll
            for (int r = 0; r < 4; r++) acc[mf][nf][r] = 0.0f;

    gemm_mainloop<AEX, NF>(smb, A_hi, A_lo, Bt_hi, Bt_lo, K, bm0, bn0, tid,
                           acc);
    gemm_epilogue<OMODE, NF>(acc, bias, O_hi, O_lo, Of, Nout, bm0, bn0, tid);
}

// ---------------------------------------------------------------------------
// Selector head body (3-stage cp.async pipeline) — runs inside fused kernel.
// ---------------------------------------------------------------------------
__device__ __forceinline__ void sel_head_body(
    char* smc, int bm0, int tid,
    const float* __restrict__ A, const float* __restrict__ B,
    const float* __restrict__ bias, float* __restrict__ C) {
    float (*As)[32][20] = reinterpret_cast<float (*)[32][20]>(smc);
    float (*Bs)[16][64] = reinterpret_cast<float (*)[16][64]>(smc + 3 * 32 * 20 * 4);

    const int tx = tid & 15;
    const int ty = tid >> 4;
    const int K = HS, N = NN;
    const int NC = K / 16;

    const uint32_t asb = smem_u32(As);
    const uint32_t bsb = smem_u32(Bs);

    auto issue = [&](int c) {
        const int s = c % 3;
        const int k0 = c * 16;
        if (tid < 128) {
            const int row = tid >> 2;
            const int q = tid & 3;
            CP16(asb + (uint32_t)(((s * 32 + row) * 20 + q * 4) * 4),
                 A + (size_t)(bm0 + row) * K + k0 + q * 4);
        }
        {
            const int kr = tid >> 4;
            const int q = tid & 15;
            CP16(bsb + (uint32_t)(((s * 16 + kr) * 64 + q * 4) * 4),
                 B + (size_t)(k0 + kr) * N + q * 4);
        }
        CP_COMMIT();
    };

    float acc[2][4] = {{0.f, 0.f, 0.f, 0.f}, {0.f, 0.f, 0.f, 0.f}};

    issue(0);
    issue(1);

    for (int c = 0; c < NC; c++) {
        const int s = c % 3;
        if (c + 1 < NC) CP_WAIT(1); else CP_WAIT(0);
        __syncthreads();
        if (c + 2 < NC) issue(c + 2);

#pragma unroll
        for (int k = 0; k < 16; k++) {
            float a0 = As[s][ty * 2][k];
            float a1 = As[s][ty * 2 + 1][k];
            float4 bv = *reinterpret_cast<const float4*>(&Bs[s][k][tx * 4]);
            acc[0][0] = fmaf(a0, bv.x, acc[0][0]);
            acc[0][1] = fmaf(a0, bv.y, acc[0][1]);
            acc[0][2] = fmaf(a0, bv.z, acc[0][2]);
            acc[0][3] = fmaf(a0, bv.w, acc[0][3]);
            acc[1][0] = fmaf(a1, bv.x, acc[1][0]);
            acc[1][1] = fmaf(a1, bv.y, acc[1][1]);
            acc[1][2] = fmaf(a1, bv.z, acc[1][2]);
            acc[1][3] = fmaf(a1, bv.w, acc[1][3]);
        }
    }

    float4 bvec = *reinterpret_cast<const float4*>(bias + tx * 4);
    float bias4[4] = {bvec.x, bvec.y, bvec.z, bvec.w};
#pragma unroll
    for (int i = 0; i < 2; i++) {
        float4 v;
        float* vp = &v.x;
#pragma unroll
        for (int j = 0; j < 4; j++) {
            float cv = acc[i][j] + bias4[j];
            vp[j] = 1.0f / (1.0f + expf(-cv));
        }
        *reinterpret_cast<float4*>(
            C + (size_t)(bm0 + ty * 2 + i) * N + tx * 4) = v;
    }
}

// ---------------------------------------------------------------------------
// RNG precompute body: one (b,n) element per thread.
// Same fp32 ops as finalize previously did -> bitwise-identical values.
// ---------------------------------------------------------------------------
__device__ __forceinline__ void rng_body(unsigned i, float* __restrict__ ea,
                                         float* __restrict__ eb,
                                         float* __restrict__ gum) {
    float ua = jax_u01(KA0, KA1, i);
    float ub = jax_u01(KB0, KB1, i);
    ea[i] = expf(-logf(-logf(ua)));
    eb[i] = expf(-logf(-logf(ub)));
    float4 g0, g1;
    float* gp = &g0.x;
#pragma unroll
    for (int c = 0; c < 4; c++) {
        float u = jax_u01(KG0, KG1, i * 8u + (unsigned)c);
        gp[c] = -logf(-logf(u));
    }
    gp = &g1.x;
#pragma unroll
    for (int c = 0; c < 4; c++) {
        float u = jax_u01(KG0, KG1, i * 8u + (unsigned)(c + 4));
        gp[c] = -logf(-logf(u));
    }
    *reinterpret_cast<float4*>(gum + (size_t)i * 8) = g0;
    *reinterpret_cast<float4*>(gum + (size_t)i * 8 + 4) = g1;
}

// ---------------------------------------------------------------------------
// FUSED gemm2 + selector head + RNG precompute. grid = (8, 128 + 32 + 256):
//   y <  128:        gemm2 tile (NF=4)
//   y in [128,160):  head block hb = (y-128)*8 + x in [0,256), 32 rows each
//   y >= 160:        rng block r = (y-160)*8 + x in [0,2048), 256 elems each
// ---------------------------------------------------------------------------
__global__ void __launch_bounds__(256, 3)
gemm2_head_kernel(const __half* __restrict__ A_hi,
                  const __half* __restrict__ A_lo,
                  const __half* __restrict__ Bt_hi,
                  const __half* __restrict__ Bt_lo,
                  const float* __restrict__ bias,
                  __half* __restrict__ O_hi, __half* __restrict__ O_lo,
                  const float* __restrict__ s1, const float* __restrict__ sw2,
                  const float* __restrict__ sb2, float* __restrict__ P,
                  float* __restrict__ ea, float* __restrict__ eb,
                  float* __restrict__ gum) {
    extern __shared__ char smc[];
    const int tid = threadIdx.x;

    if (blockIdx.y >= 160) {
        const int r = (blockIdx.y - 160) * 8 + blockIdx.x;   // 0..2047
        rng_body((unsigned)(r * 256 + tid), ea, eb, gum);
        return;
    }
    if (blockIdx.y >= 128) {
        const int hb = (blockIdx.y - 128) * 8 + blockIdx.x;  // 0..255
        sel_head_body(smc, hb * 32, tid, s1, sw2, sb2, P);
        return;
    }

    const uint32_t smb = smem_u32(smc);
    const int bm0 = blockIdx.y * 64;
    const int bn0 = blockIdx.x * 128;

    float acc[2][4][4];
#pragma unroll
    for (int mf = 0; mf < 2; mf++)
#pragma unroll
        for (int nf = 0; nf < 4; nf++)
#pragma unroll
            for (int r = 0; r < 4; r++) acc[mf][nf][r] = 0.0f;

    gemm_mainloop<false, 4>(smb, A_hi, A_lo, Bt_hi, Bt_lo, HP, bm0, bn0, tid,
                            acc);
    gemm_epilogue<0, 4>(acc, bias, O_hi, O_lo, nullptr, HP, bm0, bn0, tid);
}

// ---------------------------------------------------------------------------
// MERGED prep kernel
// ---------------------------------------------------------------------------
__global__ void __launch_bounds__(256)
prep_kernel(const float* __restrict__ x, __half* __restrict__ xh,
            const float* __restrict__ pb1, const float* __restrict__ sb1,
            float* __restrict__ bias_l1,
            const float* __restrict__ pw1, const float* __restrict__ sw1,
            const float* __restrict__ pw2, const float* __restrict__ pw3,
            const float* __restrict__ pw4,
            __half* __restrict__ bt_hi, __half* __restrict__ bt_lo) {
    if (blockIdx.x < 2048) {
        const int t = blockIdx.x * 256 + threadIdx.x;
        const float4 a = *reinterpret_cast<const float4*>(x + (size_t)t * 8);
        const float4 b = *reinterpret_cast<const float4*>(x + (size_t)t * 8 + 4);
        __half2 o[4];
        o[0] = __halves2half2(__float2half_rn(a.x), __float2half_rn(a.y));
        o[1] = __halves2half2(__float2half_rn(a.z), __float2half_rn(a.w));
        o[2] = __halves2half2(__float2half_rn(b.x), __float2half_rn(b.y));
        o[3] = __halves2half2(__float2half_rn(b.z), __float2half_rn(b.w));
        *reinterpret_cast<uint4*>(xh + (size_t)t * 8) =
            *reinterpret_cast<uint4*>(o);
        if (t < HP + HS)
            bias_l1[t] = (t < HP) ? pb1[t] : sb1[t - HP];
        return;
    }

    const int b = blockIdx.x - 2048;
    const float* W;
    int off, K, N, lb;
    if (b < 512)        { W = pw1; off = OF_PW1; K = 512;  N = 1024; lb = b; }
    else if (b < 768)   { W = sw1; off = OF_SW1; K = 512;  N = 512;  lb = b - 512; }
    else if (b < 1792)  { W = pw2; off = OF_PW2; K = 1024; N = 1024; lb = b - 768; }
    else if (b < 2816)  { W = pw3; off = OF_PW3; K = 1024; N = 1024; lb = b - 1792; }
    else                { W = pw4; off = OF_PW4; K = 1024; N = 512;  lb = b - 2816; }
    const int kt = K >> 5;
    const int kb = (lb % kt) * 32;
    const int nb = (lb / kt) * 32;

    __shared__ float t[32][33];
    const int tx = threadIdx.x & 31;
    const int ty = threadIdx.x >> 5;
#pragma unroll
    for (int r = ty; r < 32; r += 8)
        t[r][tx] = W[(size_t)(kb + r) * N + nb + tx];
    __syncthreads();
#pragma unroll
    for (int r = ty; r < 32; r += 8) {
        float wv = t[tx][r];
        __half h, lo;
        split_h(wv, h, lo);
        size_t o = (size_t)off + (size_t)(nb + r) * K + kb + tx;
        bt_hi[o] = h;
        bt_lo[o] = lo;
    }
}

// ---------------------------------------------------------------------------
// Fused elementwise tail (+ truth_x passthrough); RNG loaded from buffers
// ---------------------------------------------------------------------------
__device__ __forceinline__ void gs8(const float* l, const float* g, float* xt) {
    float m = l[0];
#pragma unroll
    for (int c = 1; c < 8; c++) m = fmaxf(m, l[c]);
    float e[8], s = 0.0f;
#pragma unroll
    for (int c = 0; c < 8; c++) { e[c] = expf(l[c] - m); s += e[c]; }
    float t[8];
#pragma unroll
    for (int c = 0; c < 8; c++) {
        float pr = e[c] / s;
        pr = 0.9f * pr + 0.0125f;
        t[c] = (logf(pr) + g[c]) / 0.7f;
    }
    float m2 = t[0];
#pragma unroll
    for (int c = 1; c < 8; c++) m2 = fmaxf(m2, t[c]);
    float e2[8], s2 = 0.0f;
#pragma unroll
    for (int c = 0; c < 8; c++) { e2[c] = expf(t[c] - m2); s2 += e2[c]; }
#pragma unroll
    for (int c = 0; c < 8; c++) xt[c] = e2[c] / s2;
}

__global__ void finalize_kernel(const float* __restrict__ x,
                                const float* __restrict__ Pm,
                                const float* __restrict__ W,
                                const float* __restrict__ truth,
                                const float* __restrict__ ea_b,
                                const float* __restrict__ eb_b,
                                const float* __restrict__ gum,
                                float* __restrict__ out_truth,
                                float* __restrict__ xcf) {
    const int b = blockIdx.x;
    const int n = threadIdx.x;
    __shared__ float sh_cst, sh_incr;

    const size_t base = (size_t)b * DD + n * CC;

    *reinterpret_cast<float4*>(out_truth + base) =
        *reinterpret_cast<const float4*>(truth + base);
    *reinterpret_cast<float4*>(out_truth + base + 4) =
        *reinterpret_cast<const float4*>(truth + base + 4);

    float4 xa = *reinterpret_cast<const float4*>(x + base);
    float4 xb = *reinterpret_cast<const float4*>(x + base + 4);
    float4 wa = *reinterpret_cast<const float4*>(W + base);
    float4 wb = *reinterpret_cast<const float4*>(W + base + 4);
    float xv[8] = {xa.x, xa.y, xa.z, xa.w, xb.x, xb.y, xb.z, xb.w};
    float Wv[8] = {wa.x, wa.y, wa.z, wa.w, wb.x, wb.y, wb.z, wb.w};

    const unsigned i = (unsigned)(b * NN + n);
    const float P = Pm[i];

    const float ea = ea_b[i];
    const float eb = eb_b[i];
    float no = P * ea / 0.7f;
    float de = no + (1.0f - P) * eb / 0.7f;
    float probs = no / de;

    float g[8];
    {
        float4 ga = *reinterpret_cast<const float4*>(gum + (size_t)i * 8);
        float4 gb = *reinterpret_cast<const float4*>(gum + (size_t)i * 8 + 4);
        g[0] = ga.x; g[1] = ga.y; g[2] = ga.z; g[3] = ga.w;
        g[4] = gb.x; g[5] = gb.y; g[6] = gb.z; g[7] = gb.w;
    }

    int curr = 0;
    {
        float m = xv[0];
#pragma unroll
        for (int c = 1; c < 8; c++)
            if (xv[c] > m) { m = xv[c]; curr = c; }
    }

    if (n == 2) {
        float xt_par[8];
        gs8(Wv, g, xt_par);
        int am = 0;
        float m = probs * xt_par[0] + (1.0f - probs) * xv[0];
#pragma unroll
        for (int c = 1; c < 8; c++) {
            float v = probs * xt_par[c] + (1.0f - probs) * xv[c];
            if (v > m) { m = v; am = c; }
        }
        int diff = am - curr;
        sh_cst  = (diff == 0) ? 1.0f : 0.0f;
        sh_incr = (diff >  0) ? 1.0f : 0.0f;
    }
    __syncthreads();
    const float cst = sh_cst;
    const float incr = sh_incr;

    float l[8];
    if (n == 0 || n == 5 || n == 10) {
#pragma unroll
        for (int c = 0; c < 8; c++) l[c] = Wv[c] + ((c < curr) ? -100.0f : 1.0f);
    } else if (n == 7) {
        const int thr = curr + 1;
        const bool inc = (incr > 0.5f);
#pragma unroll
        for (int c = 0; c < 8; c++)
            l[c] = Wv[c] + ((inc && c < thr) ? -100.0f : 1.0f);
    } else {
#pragma unroll
        for (int c = 0; c < 8; c++) l[c] = Wv[c];
    }

    float xt[8];
    gs8(l, g, xt);

    float p2 = probs;
    if (n == 7) {
        float pc = probs * (1.0f - cst);
        pc = pc + incr;
        p2 = fminf(fmaxf(pc, 0.0f), 1.0f);
    }

    float4 oa, ob;
    float* op = &oa.x;
#pragma unroll
    for (int c = 0; c < 4; c++) op[c] = p2 * xt[c] + (1.0f - p2) * xv[c];
    op = &ob.x;
#pragma unroll
    for (int c = 0; c < 4; c++) op[c] = p2 * xt[c + 4] + (1.0f - p2) * xv[c + 4];
    *reinterpret_cast<float4*>(xcf + base) = oa;
    *reinterpret_cast<float4*>(xcf + base + 4) = ob;
}

// ---------------------------------------------------------------------------
// Launch
// ---------------------------------------------------------------------------
extern "C" void kernel_launch(void* const* d_in, const int* in_sizes, int n_in,
                              void* d_out, int out_size) {
    const float* x     = (const float*)d_in[0];
    const float* truth = (const float*)d_in[1];
    const float* sw1   = (const float*)d_in[2];
    const float* sb1   = (const float*)d_in[3];
    const float* sw2   = (const float*)d_in[4];
    const float* sb2   = (const float*)d_in[5];
    const float* pw1   = (const float*)d_in[6];
    const float* pb1   = (const float*)d_in[7];
    const float* pw2   = (const float*)d_in[8];
    const float* pb2   = (const float*)d_in[9];
    const float* pw3   = (const float*)d_in[10];
    const float* pb3   = (const float*)d_in[11];
    const float* pw4   = (const float*)d_in[12];
    const float* pb4   = (const float*)d_in[13];

    float* out       = (float*)d_out;
    float* out_truth = out;
    float* out_xcf   = out + BD_ELEMS;
    float* out_P     = out + 2 * (size_t)BD_ELEMS;
    float* out_W     = out + 2 * (size_t)BD_ELEMS + BN_ELEMS;

    __half *a_hi, *a_lo, *b_hi, *b_lo, *xh, *wt_hi, *wt_lo;
    float *s1, *bias_l1, *ea, *eb, *gum;
    cudaGetSymbolAddress((void**)&a_hi, g_a_hi);
    cudaGetSymbolAddress((void**)&a_lo, g_a_lo);
    cudaGetSymbolAddress((void**)&b_hi, g_b_hi);
    cudaGetSymbolAddress((void**)&b_lo, g_b_lo);
    cudaGetSymbolAddress((void**)&xh,   g_xh);
    cudaGetSymbolAddress((void**)&s1,   g_s1);
    cudaGetSymbolAddress((void**)&wt_hi, g_wt_hi);
    cudaGetSymbolAddress((void**)&wt_lo, g_wt_lo);
    cudaGetSymbolAddress((void**)&bias_l1, g_bias_l1);
    cudaGetSymbolAddress((void**)&ea, g_ea);
    cudaGetSymbolAddress((void**)&eb, g_eb);
    cudaGetSymbolAddress((void**)&gum, g_gum);

    constexpr int SM4 = TileCfg<4>::SMEM;   // 73728
    constexpr int SM2 = TileCfg<2>::SMEM;   // 49152
    cudaFuncSetAttribute(gemm_h<true, 2, 4>,
                         cudaFuncAttributeMaxDynamicSharedMemorySize, SM4);
    cudaFuncSetAttribute(gemm_h<false, 0, 4>,
                         cudaFuncAttributeMaxDynamicSharedMemorySize, SM4);
    cudaFuncSetAttribute(gemm_h<false, 1, 2>,
                         cudaFuncAttributeMaxDynamicSharedMemorySize, SM2);
    cudaFuncSetAttribute(gemm2_head_kernel,
                         cudaFuncAttributeMaxDynamicSharedMemorySize, SM4);

    // Prep: x->fp16 + bias concat + all weight splits, one launch
    prep_kernel<<<5376, 256>>>(x, xh, pb1, sb1, bias_l1,
                               pw1, sw1, pw2, pw3, pw4, wt_hi, wt_lo);

    // L1 (pw1 + sw1 merged, AEX, mixed epilogue) -- NF=4
    gemm_h<true, 2, 4><<<dim3((HP + HS) / 128, BB / 64), 256, SM4>>>(
        xh, nullptr, wt_hi, wt_lo, bias_l1, a_hi, a_lo, s1, DD, HP);

    // gemm2 FUSED with selector head + RNG precompute
    gemm2_head_kernel<<<dim3(HP / 128, BB / 64 + 32 + 256), 256, SM4>>>(
        a_hi, a_lo, wt_hi + OF_PW2, wt_lo + OF_PW2, pb2, b_hi, b_lo,
        s1, sw2, sb2, out_P, ea, eb, gum);

    // gemm3 (NF=4), gemm4 (NF=2: grid 1024, fixes 1.15-wave quantization)
    gemm_h<false, 0, 4><<<dim3(HP / 128, BB / 64), 256, SM4>>>(
        b_hi, b_lo, wt_hi + OF_PW3, wt_lo + OF_PW3, pb3, a_hi, a_lo, nullptr,
        HP, HP);
    gemm_h<false, 1, 2><<<dim3(DD / 64, BB / 64), 256, SM2>>>(
        a_hi, a_lo, wt_hi + OF_PW4, wt_lo + OF_PW4, pb4, nullptr, nullptr,
        out_W, HP, DD);

    // Fused tail (+ truth passthrough), RNG from buffers
    finalize_kernel<<<BB, NN>>>(x, out_P, out_W, truth, ea, eb, gum,
                                out_truth, out_xcf);
}

// round 16
// speedup vs baseline: 1.0647x; 1.0041x over previous
#include <cuda_runtime.h>
#include <cuda_fp16.h>
#include <cstdint>
#include <math.h>

// ---------------------------------------------------------------------------
// Problem constants
// ---------------------------------------------------------------------------
#define BB 8192
#define NN 64
#define CC 8
#define DD (NN * CC)        // 512
#define HP 1024
#define HS 512
#define BD_ELEMS (BB * DD)  // 4,194,304
#define BN_ELEMS (BB * NN)  // 524,288

// ---------------------------------------------------------------------------
// Scratch (allocation-free: __device__ globals)
// ---------------------------------------------------------------------------
__device__ __half g_a_hi[BB * HP];
__device__ __half g_a_lo[BB * HP];
__device__ __half g_b_hi[BB * HP];
__device__ __half g_b_lo[BB * HP];
__device__ __half g_xh[BB * DD];
__device__ float  g_s1[BB * HS];
__device__ float  g_bias_l1[HP + HS];   // pb1 ++ sb1
__device__ float  g_ea[BN_ELEMS];
__device__ float  g_eb[BN_ELEMS];
__device__ float  g_gum[BN_ELEMS * 8];

// Transposed + split weights, packed (Bt[n][k] layout), fp16 hi/lo.
#define OF_PW1 0
#define OF_SW1 524288
#define OF_PW2 786432
#define OF_PW3 1835008
#define OF_PW4 2883584
#define WT_TOTAL 3407872
__device__ __half g_wt_hi[WT_TOTAL];
__device__ __half g_wt_lo[WT_TOTAL];

// ---------------------------------------------------------------------------
// Threefry-2x32-20 (JAX)
// ---------------------------------------------------------------------------
struct TFK { unsigned a, b; };

__host__ __device__ constexpr unsigned tf_rotl(unsigned v, int r) {
    return (v << r) | (v >> (32 - r));
}

__host__ __device__ constexpr TFK tf2x32(unsigned k0, unsigned k1,
                                         unsigned x0, unsigned x1) {
    unsigned k2 = k0 ^ k1 ^ 0x1BD11BDAu;
    x0 += k0; x1 += k1;
    x0 += x1; x1 = tf_rotl(x1, 13); x1 ^= x0;
    x0 += x1; x1 = tf_rotl(x1, 15); x1 ^= x0;
    x0 += x1; x1 = tf_rotl(x1, 26); x1 ^= x0;
    x0 += x1; x1 = tf_rotl(x1,  6); x1 ^= x0;
    x0 += k1; x1 += k2 + 1u;
    x0 += x1; x1 = tf_rotl(x1, 17); x1 ^= x0;
    x0 += x1; x1 = tf_rotl(x1, 29); x1 ^= x0;
    x0 += x1; x1 = tf_rotl(x1, 16); x1 ^= x0;
    x0 += x1; x1 = tf_rotl(x1, 24); x1 ^= x0;
    x0 += k2; x1 += k0 + 2u;
    x0 += x1; x1 = tf_rotl(x1, 13); x1 ^= x0;
    x0 += x1; x1 = tf_rotl(x1, 15); x1 ^= x0;
    x0 += x1; x1 = tf_rotl(x1, 26); x1 ^= x0;
    x0 += x1; x1 = tf_rotl(x1,  6); x1 ^= x0;
    x0 += k0; x1 += k1 + 3u;
    x0 += x1; x1 = tf_rotl(x1, 17); x1 ^= x0;
    x0 += x1; x1 = tf_rotl(x1, 29); x1 ^= x0;
    x0 += x1; x1 = tf_rotl(x1, 16); x1 ^= x0;
    x0 += x1; x1 = tf_rotl(x1, 24); x1 ^= x0;
    x0 += k1; x1 += k2 + 4u;
    x0 += x1; x1 = tf_rotl(x1, 13); x1 ^= x0;
    x0 += x1; x1 = tf_rotl(x1, 15); x1 ^= x0;
    x0 += x1; x1 = tf_rotl(x1, 26); x1 ^= x0;
    x0 += x1; x1 = tf_rotl(x1,  6); x1 ^= x0;
    x0 += k2; x1 += k0 + 5u;
    return TFK{x0, x1};
}

constexpr unsigned KA0 = tf2x32(0u, 42u, 0u, 0u).a;
constexpr unsigned KA1 = tf2x32(0u, 42u, 0u, 0u).b;
constexpr unsigned KB0 = tf2x32(0u, 42u, 0u, 1u).a;
constexpr unsigned KB1 = tf2x32(0u, 42u, 0u, 1u).b;
constexpr unsigned KG0 = tf2x32(0u, 42u, 0u, 2u).a;
constexpr unsigned KG1 = tf2x32(0u, 42u, 0u, 2u).b;

__device__ __forceinline__ float jax_u01(unsigned k0, unsigned k1, unsigned idx) {
    TFK r = tf2x32(k0, k1, 0u, idx);
    unsigned bits = r.a ^ r.b;
    float f = __uint_as_float((bits >> 9) | 0x3f800000u) - 1.0f;
    f = f + 1e-8f;
    return fmaxf(1e-8f, f);
}

// ---------------------------------------------------------------------------
// Helpers
// ---------------------------------------------------------------------------
__device__ __forceinline__ uint32_t smem_u32(const void* p) {
    uint32_t a;
    asm("{ .reg .u64 t; cvta.to.shared.u64 t, %1; cvt.u32.u64 %0, t; }"
        : "=r"(a) : "l"(p));
    return a;
}

#define CP16(dst_u32, src_ptr) \
    asm volatile("cp.async.cg.shared.global [%0], [%1], 16;" \
                 :: "r"(dst_u32), "l"(src_ptr) : "memory")
#define CP_COMMIT() asm volatile("cp.async.commit_group;" ::: "memory")
#define CP_WAIT(n)  asm volatile("cp.async.wait_group %0;" :: "n"(n) : "memory")

__device__ __forceinline__ void mma16(float* d, const uint32_t* a,
                                      const uint32_t* b) {
    asm volatile(
        "mma.sync.aligned.m16n8k16.row.col.f32.f16.f16.f32 "
        "{%0,%1,%2,%3}, {%4,%5,%6,%7}, {%8,%9}, {%0,%1,%2,%3};"
        : "+f"(d[0]), "+f"(d[1]), "+f"(d[2]), "+f"(d[3])
        : "r"(a[0]), "r"(a[1]), "r"(a[2]), "r"(a[3]), "r"(b[0]), "r"(b[1]));
}

__device__ __forceinline__ void ldsm_x4(uint32_t* r, uint32_t addr) {
    asm volatile(
        "ldmatrix.sync.aligned.m8n8.x4.shared.b16 {%0,%1,%2,%3}, [%4];"
        : "=r"(r[0]), "=r"(r[1]), "=r"(r[2]), "=r"(r[3]) : "r"(addr));
}

__device__ __forceinline__ void split_h(float y, __half& h, __half& l) {
    h = __float2half_rn(y);
    l = __float2half_rn(y - __half2float(h));
}

// ---------------------------------------------------------------------------
// fp16-split GEMM mainloop. BM=64, BN=32*NF, BK=32, 256 thr, warps 2x4,
// warp tile 32 x (8*NF). Term-major MMA issue (dependency distance 2*NF).
// Packed 64B rows + XOR swizzle, 3 stages, one barrier/chunk, prefetch 2.
// ---------------------------------------------------------------------------
#define TILE_AT 4096                    // 64 rows x 64 bytes

template <int NF> struct TileCfg {
    static constexpr int TILE_BT = 32 * NF * 64;
    static constexpr int T_AH = 0;
    static constexpr int T_AL = TILE_AT;
    static constexpr int T_BH = 2 * TILE_AT;
    static constexpr int T_BL = 2 * TILE_AT + TILE_BT;
    static constexpr int STAGE = 2 * TILE_AT + 2 * TILE_BT;
    static constexpr int SMEM = 3 * STAGE;
};
// NF=4: STAGE=24576, SMEM=73728.  NF=2: STAGE=16384, SMEM=49152.

template <bool AEX, int NF>
__device__ __forceinline__ void issue_chunk_h(
    uint32_t smb, int c,
    const __half* __restrict__ A_hi, const __half* __restrict__ A_lo,
    const __half* __restrict__ B_hi, const __half* __restrict__ B_lo,
    int K, int bm0, int bn0, int tid) {
    using C_ = TileCfg<NF>;
    const int k0 = c * 32;
    const uint32_t sb = smb + (uint32_t)((c % 3) * C_::STAGE);
    {
        const int row = tid >> 2;
        const int q = tid & 3;
        const uint32_t doff =
            (uint32_t)(row * 64 + ((q ^ ((row >> 1) & 3)) * 16));
        CP16(sb + C_::T_AH + doff, A_hi + (size_t)(bm0 + row) * K + k0 + q * 8);
        if (!AEX)
            CP16(sb + C_::T_AL + doff,
                 A_lo + (size_t)(bm0 + row) * K + k0 + q * 8);
    }
#pragma unroll
    for (int i = 0; i < NF / 2; i++) {
        const int f = tid + i * 256;
        const int row = f >> 2;
        const int q = f & 3;
        const uint32_t doff =
            (uint32_t)(row * 64 + ((q ^ ((row >> 1) & 3)) * 16));
        CP16(sb + C_::T_BH + doff, B_hi + (size_t)(bn0 + row) * K + k0 + q * 8);
        CP16(sb + C_::T_BL + doff, B_lo + (size_t)(bn0 + row) * K + k0 + q * 8);
    }
    CP_COMMIT();
}

template <bool AEX, int NF>
__device__ __forceinline__ void gemm_mainloop(
    uint32_t smb, const __half* __restrict__ A_hi,
    const __half* __restrict__ A_lo, const __half* __restrict__ Bt_hi,
    const __half* __restrict__ Bt_lo, int K, int bm0, int bn0, int tid,
    float acc[2][NF][4]) {
    using C_ = TileCfg<NF>;
    const int l = tid & 31;
    const int warp = tid >> 5;
    const int wm = warp >> 2;
    const int wn = warp & 3;
    const int NC = K >> 5;

    issue_chunk_h<AEX, NF>(smb, 0, A_hi, A_lo, Bt_hi, Bt_lo, K, bm0, bn0, tid);
    if (NC > 1)
        issue_chunk_h<AEX, NF>(smb, 1, A_hi, A_lo, Bt_hi, Bt_lo, K, bm0, bn0,
                               tid);

    const int swz = (l >> 1) & 3;
    const uint32_t arow = (uint32_t)((wm * 32 + (l & 15)) * 64);
    const int acb = l >> 4;
    const uint32_t brow =
        (uint32_t)((wn * NF * 8 + ((l >> 4) & 1) * 8 + (l & 7)) * 64);
    const int bcb = (l >> 3) & 1;

    for (int c = 0; c < NC; c++) {
        if (c + 1 < NC) {
            CP_WAIT(1);
        } else {
            CP_WAIT(0);
        }
        __syncthreads();
        if (c + 2 < NC)
            issue_chunk_h<AEX, NF>(smb, c + 2, A_hi, A_lo, Bt_hi, Bt_lo, K,
                                   bm0, bn0, tid);

        const uint32_t stage = smb + (uint32_t)((c % 3) * C_::STAGE);
        const uint32_t baseAh = stage + C_::T_AH + arow;
        const uint32_t baseAl = stage + C_::T_AL + arow;
        const uint32_t baseBh = stage + C_::T_BH + brow;
        const uint32_t baseBl = stage + C_::T_BL + brow;

#pragma unroll
        for (int ks = 0; ks < 2; ks++) {
            const uint32_t aco = (uint32_t)(((ks * 2 + acb) ^ swz) * 16);
            const uint32_t bco = (uint32_t)(((ks * 2 + bcb) ^ swz) * 16);
            uint32_t bh[NF][2], bl[NF][2];
#pragma unroll
            for (int j = 0; j < NF / 2; j++) {
                uint32_t t[4];
                ldsm_x4(t, baseBh + (uint32_t)(j * 16 * 64) + bco);
                bh[2 * j][0] = t[0]; bh[2 * j][1] = t[1];
                bh[2 * j + 1][0] = t[2]; bh[2 * j + 1][1] = t[3];
                ldsm_x4(t, baseBl + (uint32_t)(j * 16 * 64) + bco);
                bl[2 * j][0] = t[0]; bl[2 * j][1] = t[1];
                bl[2 * j + 1][0] = t[2]; bl[2 * j + 1][1] = t[3];
            }
            uint32_t ah[2][4], al[2][4];
#pragma unroll
            for (int mf = 0; mf < 2; mf++) {
                ldsm_x4(ah[mf], baseAh + (uint32_t)(mf * 16 * 64) + aco);
                if (!AEX)
                    ldsm_x4(al[mf], baseAl + (uint32_t)(mf * 16 * 64) + aco);
            }
            // Term-major: per-acc order unchanged (hh, hl, lh) -> bitwise
            // identical, but dependency distance between writes to the same
            // accumulator grows from 1 to 2*NF issues.
#pragma unroll
            for (int mf = 0; mf < 2; mf++)
#pragma unroll
                for (int nf = 0; nf < NF; nf++)
                    mma16(acc[mf][nf], ah[mf], bh[nf]);
#pragma unroll
            for (int mf = 0; mf < 2; mf++)
#pragma unroll
                for (int nf = 0; nf < NF; nf++)
                    mma16(acc[mf][nf], ah[mf], bl[nf]);
            if (!AEX) {
#pragma unroll
                for (int mf = 0; mf < 2; mf++)
#pragma unroll
                    for (int nf = 0; nf < NF; nf++)
                        mma16(acc[mf][nf], al[mf], bh[nf]);
            }
        }
    }
    __syncthreads();
}

// Epilogue
template <int OMODE, int NF>   // 0 = relu+split, 1 = fp32, 2 = mixed L1
__device__ __forceinline__ void gemm_epilogue(
    float acc[2][NF][4], const float* __restrict__ bias,
    __half* __restrict__ O_hi, __half* __restrict__ O_lo,
    float* __restrict__ Of, int Nout, int bm0, int bn0, int tid) {
    const int l = tid & 31;
    const int warp = tid >> 5;
    const int wm = warp >> 2;
    const int wn = warp & 3;
    const int rA = l >> 2;
    const int cK = l & 3;
    const bool f32_region = (OMODE == 1) || (OMODE == 2 && bn0 >= HP);
    const int ow = (OMODE == 2) ? (f32_region ? HS : HP) : Nout;
    const int cbase = (OMODE == 2 && f32_region) ? (bn0 - HP) : bn0;

#pragma unroll
    for (int nf = 0; nf < NF; nf++) {
        const int gcol = bn0 + wn * NF * 8 + nf * 8 + 2 * cK;
        const int col = cbase + wn * NF * 8 + nf * 8 + 2 * cK;
        const float2 bv = *reinterpret_cast<const float2*>(bias + gcol);
#pragma unroll
        for (int mf = 0; mf < 2; mf++) {
            const int ra = bm0 + wm * 32 + mf * 16 + rA;
            float y[4];
            y[0] = acc[mf][nf][0] + bv.x;
            y[1] = acc[mf][nf][1] + bv.y;
            y[2] = acc[mf][nf][2] + bv.x;
            y[3] = acc[mf][nf][3] + bv.y;
            if (OMODE != 1) {
#pragma unroll
                for (int r = 0; r < 4; r++) y[r] = fmaxf(y[r], 0.0f);
            }
            if (!f32_region && OMODE != 1) {
                __half h[4], lo[4];
#pragma unroll
                for (int r = 0; r < 4; r++) split_h(y[r], h[r], lo[r]);
                *reinterpret_cast<__half2*>(O_hi + (size_t)ra * ow + col) =
                    __halves2half2(h[0], h[1]);
                *reinterpret_cast<__half2*>(O_hi + (size_t)(ra + 8) * ow + col) =
                    __halves2half2(h[2], h[3]);
                *reinterpret_cast<__half2*>(O_lo + (size_t)ra * ow + col) =
                    __halves2half2(lo[0], lo[1]);
                *reinterpret_cast<__half2*>(O_lo + (size_t)(ra + 8) * ow + col) =
                    __halves2half2(lo[2], lo[3]);
            } else {
                *reinterpret_cast<float2*>(Of + (size_t)ra * ow + col) =
                    make_float2(y[0], y[1]);
                *reinterpret_cast<float2*>(Of + (size_t)(ra + 8) * ow + col) =
                    make_float2(y[2], y[3]);
            }
        }
    }
}

// ---------------------------------------------------------------------------
// Weight transpose+split body: one 32x32 tile, using caller-provided smem.
// b is the absolute block index in the full 3328-tile numbering.
// ---------------------------------------------------------------------------
__device__ __forceinline__ void wsplit_body(
    char* smc, int b, int tid,
    const float* __restrict__ pw1, const float* __restrict__ sw1,
    const float* __restrict__ pw2, const float* __restrict__ pw3,
    const float* __restrict__ pw4,
    __half* __restrict__ bt_hi, __half* __restrict__ bt_lo) {
    float (*t)[33] = reinterpret_cast<float (*)[33]>(smc);
    const float* W;
    int off, K, N, lb;
    if (b < 512)        { W = pw1; off = OF_PW1; K = 512;  N = 1024; lb = b; }
    else if (b < 768)   { W = sw1; off = OF_SW1; K = 512;  N = 512;  lb = b - 512; }
    else if (b < 1792)  { W = pw2; off = OF_PW2; K = 1024; N = 1024; lb = b - 768; }
    else if (b < 2816)  { W = pw3; off = OF_PW3; K = 1024; N = 1024; lb = b - 1792; }
    else                { W = pw4; off = OF_PW4; K = 1024; N = 512;  lb = b - 2816; }
    const int kt = K >> 5;
    const int kb = (lb % kt) * 32;
    const int nb = (lb / kt) * 32;

    const int tx = tid & 31;
    const int ty = tid >> 5;
#pragma unroll
    for (int r = ty; r < 32; r += 8)
        t[r][tx] = W[(size_t)(kb + r) * N + nb + tx];
    __syncthreads();
#pragma unroll
    for (int r = ty; r < 32; r += 8) {
        float wv = t[tx][r];
        __half h, lo;
        split_h(wv, h, lo);
        size_t o = (size_t)off + (size_t)(nb + r) * K + kb + tx;
        bt_hi[o] = h;
        bt_lo[o] = lo;
    }
}

// ---------------------------------------------------------------------------
// Plain GEMM kernels (L3 split NF=4, L4 fp32 NF=2)
// ---------------------------------------------------------------------------
template <bool AEX, int OMODE, int NF>
__global__ void __launch_bounds__(256, 3)
gemm_h(const __half* __restrict__ A_hi, const __half* __restrict__ A_lo,
       const __half* __restrict__ Bt_hi, const __half* __restrict__ Bt_lo,
       const float* __restrict__ bias,
       __half* __restrict__ O_hi, __half* __restrict__ O_lo,
       float* __restrict__ Of,
       int K, int Nout) {
    extern __shared__ __half smh[];
    const uint32_t smb = smem_u32(smh);
    const int tid = threadIdx.x;
    const int bm0 = blockIdx.y * 64;
    const int bn0 = blockIdx.x * (NF * 32);

    float acc[2][NF][4];
#pragma unroll
    for (int mf = 0; mf < 2; mf++)
#pragma unroll
        for (int nf = 0; nf < NF; nf++)
#pragma unroll
            for (int r = 0; r < 4; r++) acc[mf][nf][r] = 0.0f;

    gemm_mainloop<AEX, NF>(smb, A_hi, A_lo, Bt_hi, Bt_lo, K, bm0, bn0, tid,
                           acc);
    gemm_epilogue<OMODE, NF>(acc, bias, O_hi, O_lo, Of, Nout, bm0, bn0, tid);
}

// ---------------------------------------------------------------------------
// FUSED L1 GEMM + pw2/pw3/pw4 weight-split filler. grid = (12, 128 + 214):
//   y < 128: L1 tile (AEX, mixed epilogue), bn0 = x*128
//   y >= 128: filler f = (y-128)*12 + x; f < 2560 -> wsplit block b = 768+f
// ---------------------------------------------------------------------------
__global__ void __launch_bounds__(256, 3)
gemm1_kernel(const __half* __restrict__ xh,
             const __half* __restrict__ Bt_hi,
             const __half* __restrict__ Bt_lo,
             const float* __restrict__ bias,
             __half* __restrict__ O_hi, __half* __restrict__ O_lo,
             float* __restrict__ s1,
             const float* __restrict__ pw1, const float* __restrict__ sw1,
             const float* __restrict__ pw2, const float* __restrict__ pw3,
             const float* __restrict__ pw4,
             __half* __restrict__ wt_hi, __half* __restrict__ wt_lo) {
    extern __shared__ char smc[];
    const int tid = threadIdx.x;

    if (blockIdx.y >= 128) {
        const int f = (blockIdx.y - 128) * 12 + blockIdx.x;
        if (f < 2560)
            wsplit_body(smc, 768 + f, tid, pw1, sw1, pw2, pw3, pw4, wt_hi,
                        wt_lo);
        return;
    }

    const uint32_t smb = smem_u32(smc);
    const int bm0 = blockIdx.y * 64;
    const int bn0 = blockIdx.x * 128;

    float acc[2][4][4];
#pragma unroll
    for (int mf = 0; mf < 2; mf++)
#pragma unroll
        for (int nf = 0; nf < 4; nf++)
#pragma unroll
            for (int r = 0; r < 4; r++) acc[mf][nf][r] = 0.0f;

    gemm_mainloop<true, 4>(smb, xh, nullptr, Bt_hi, Bt_lo, DD, bm0, bn0, tid,
                           acc);
    gemm_epilogue<2, 4>(acc, bias, O_hi, O_lo, s1, HP, bm0, bn0, tid);
}

// ---------------------------------------------------------------------------
// Selector head body (3-stage cp.async pipeline)
// ---------------------------------------------------------------------------
__device__ __forceinline__ void sel_head_body(
    char* smc, int bm0, int tid,
    const float* __restrict__ A, const float* __restrict__ B,
    const float* __restrict__ bias, float* __restrict__ C) {
    float (*As)[32][20] = reinterpret_cast<float (*)[32][20]>(smc);
    float (*Bs)[16][64] = reinterpret_cast<float (*)[16][64]>(smc + 3 * 32 * 20 * 4);

    const int tx = tid & 15;
    const int ty = tid >> 4;
    const int K = HS, N = NN;
    const int NC = K / 16;

    const uint32_t asb = smem_u32(As);
    const uint32_t bsb = smem_u32(Bs);

    auto issue = [&](int c) {
        const int s = c % 3;
        const int k0 = c * 16;
        if (tid < 128) {
            const int row = tid >> 2;
            const int q = tid & 3;
            CP16(asb + (uint32_t)(((s * 32 + row) * 20 + q * 4) * 4),
                 A + (size_t)(bm0 + row) * K + k0 + q * 4);
        }
        {
            const int kr = tid >> 4;
            const int q = tid & 15;
            CP16(bsb + (uint32_t)(((s * 16 + kr) * 64 + q * 4) * 4),
                 B + (size_t)(k0 + kr) * N + q * 4);
        }
        CP_COMMIT();
    };

    float acc[2][4] = {{0.f, 0.f, 0.f, 0.f}, {0.f, 0.f, 0.f, 0.f}};

    issue(0);
    issue(1);

    for (int c = 0; c < NC; c++) {
        const int s = c % 3;
        if (c + 1 < NC) CP_WAIT(1); else CP_WAIT(0);
        __syncthreads();
        if (c + 2 < NC) issue(c + 2);

#pragma unroll
        for (int k = 0; k < 16; k++) {
            float a0 = As[s][ty * 2][k];
            float a1 = As[s][ty * 2 + 1][k];
            float4 bv = *reinterpret_cast<const float4*>(&Bs[s][k][tx * 4]);
            acc[0][0] = fmaf(a0, bv.x, acc[0][0]);
            acc[0][1] = fmaf(a0, bv.y, acc[0][1]);
            acc[0][2] = fmaf(a0, bv.z, acc[0][2]);
            acc[0][3] = fmaf(a0, bv.w, acc[0][3]);
            acc[1][0] = fmaf(a1, bv.x, acc[1][0]);
            acc[1][1] = fmaf(a1, bv.y, acc[1][1]);
            acc[1][2] = fmaf(a1, bv.z, acc[1][2]);
            acc[1][3] = fmaf(a1, bv.w, acc[1][3]);
        }
    }

    float4 bvec = *reinterpret_cast<const float4*>(bias + tx * 4);
    float bias4[4] = {bvec.x, bvec.y, bvec.z, bvec.w};
#pragma unroll
    for (int i = 0; i < 2; i++) {
        float4 v;
        float* vp = &v.x;
#pragma unroll
        for (int j = 0; j < 4; j++) {
            float cv = acc[i][j] + bias4[j];
            vp[j] = 1.0f / (1.0f + expf(-cv));
        }
        *reinterpret_cast<float4*>(
            C + (size_t)(bm0 + ty * 2 + i) * N + tx * 4) = v;
    }
}

// ---------------------------------------------------------------------------
// RNG precompute body (bitwise-identical values to in-finalize computation)
// ---------------------------------------------------------------------------
__device__ __forceinline__ void rng_body(unsigned i, float* __restrict__ ea,
                                         float* __restrict__ eb,
                                         float* __restrict__ gum) {
    float ua = jax_u01(KA0, KA1, i);
    float ub = jax_u01(KB0, KB1, i);
    ea[i] = expf(-logf(-logf(ua)));
    eb[i] = expf(-logf(-logf(ub)));
    float4 g0, g1;
    float* gp = &g0.x;
#pragma unroll
    for (int c = 0; c < 4; c++) {
        float u = jax_u01(KG0, KG1, i * 8u + (unsigned)c);
        gp[c] = -logf(-logf(u));
    }
    gp = &g1.x;
#pragma unroll
    for (int c = 0; c < 4; c++) {
        float u = jax_u01(KG0, KG1, i * 8u + (unsigned)(c + 4));
        gp[c] = -logf(-logf(u));
    }
    *reinterpret_cast<float4*>(gum + (size_t)i * 8) = g0;
    *reinterpret_cast<float4*>(gum + (size_t)i * 8 + 4) = g1;
}

// ---------------------------------------------------------------------------
// FUSED gemm2 + selector head + RNG precompute. grid = (8, 128 + 32 + 256)
// ---------------------------------------------------------------------------
__global__ void __launch_bounds__(256, 3)
gemm2_head_kernel(const __half* __restrict__ A_hi,
                  const __half* __restrict__ A_lo,
                  const __half* __restrict__ Bt_hi,
                  const __half* __restrict__ Bt_lo,
                  const float* __restrict__ bias,
                  __half* __restrict__ O_hi, __half* __restrict__ O_lo,
                  const float* __restrict__ s1, const float* __restrict__ sw2,
                  const float* __restrict__ sb2, float* __restrict__ P,
                  float* __restrict__ ea, float* __restrict__ eb,
                  float* __restrict__ gum) {
    extern __shared__ char smc[];
    const int tid = threadIdx.x;

    if (blockIdx.y >= 160) {
        const int r = (blockIdx.y - 160) * 8 + blockIdx.x;
        rng_body((unsigned)(r * 256 + tid), ea, eb, gum);
        return;
    }
    if (blockIdx.y >= 128) {
        const int hb = (blockIdx.y - 128) * 8 + blockIdx.x;
        sel_head_body(smc, hb * 32, tid, s1, sw2, sb2, P);
        return;
    }

    const uint32_t smb = smem_u32(smc);
    const int bm0 = blockIdx.y * 64;
    const int bn0 = blockIdx.x * 128;

    float acc[2][4][4];
#pragma unroll
    for (int mf = 0; mf < 2; mf++)
#pragma unroll
        for (int nf = 0; nf < 4; nf++)
#pragma unroll
            for (int r = 0; r < 4; r++) acc[mf][nf][r] = 0.0f;

    gemm_mainloop<false, 4>(smb, A_hi, A_lo, Bt_hi, Bt_lo, HP, bm0, bn0, tid,
                            acc);
    gemm_epilogue<0, 4>(acc, bias, O_hi, O_lo, nullptr, HP, bm0, bn0, tid);
}

// ---------------------------------------------------------------------------
// Prep 1: x->fp16 (+ bias concat) + pw1/sw1 weight splits (768 blocks)
// ---------------------------------------------------------------------------
__global__ void __launch_bounds__(256)
prep1_kernel(const float* __restrict__ x, __half* __restrict__ xh,
             const float* __restrict__ pb1, const float* __restrict__ sb1,
             float* __restrict__ bias_l1,
             const float* __restrict__ pw1, const float* __restrict__ sw1,
             __half* __restrict__ bt_hi, __half* __restrict__ bt_lo) {
    __shared__ float tbuf[32][33];
    if (blockIdx.x < 2048) {
        const int t = blockIdx.x * 256 + threadIdx.x;
        const float4 a = *reinterpret_cast<const float4*>(x + (size_t)t * 8);
        const float4 b = *reinterpret_cast<const float4*>(x + (size_t)t * 8 + 4);
        __half2 o[4];
        o[0] = __halves2half2(__float2half_rn(a.x), __float2half_rn(a.y));
        o[1] = __halves2half2(__float2half_rn(a.z), __float2half_rn(a.w));
        o[2] = __halves2half2(__float2half_rn(b.x), __float2half_rn(b.y));
        o[3] = __halves2half2(__float2half_rn(b.z), __float2half_rn(b.w));
        *reinterpret_cast<uint4*>(xh + (size_t)t * 8) =
            *reinterpret_cast<uint4*>(o);
        if (t < HP + HS)
            bias_l1[t] = (t < HP) ? pb1[t] : sb1[t - HP];
        return;
    }
    // pw1 (blocks 0..511) and sw1 (512..767)
    wsplit_body(reinterpret_cast<char*>(tbuf), blockIdx.x - 2048,
                threadIdx.x, pw1, sw1, nullptr, nullptr, nullptr, bt_hi,
                bt_lo);
}

// ---------------------------------------------------------------------------
// Fused elementwise tail (+ truth_x passthrough); RNG from buffers
// ---------------------------------------------------------------------------
__device__ __forceinline__ void gs8(const float* l, const float* g, float* xt) {
    float m = l[0];
#pragma unroll
    for (int c = 1; c < 8; c++) m = fmaxf(m, l[c]);
    float e[8], s = 0.0f;
#pragma unroll
    for (int c = 0; c < 8; c++) { e[c] = expf(l[c] - m); s += e[c]; }
    float t[8];
#pragma unroll
    for (int c = 0; c < 8; c++) {
        float pr = e[c] / s;
        pr = 0.9f * pr + 0.0125f;
        t[c] = (logf(pr) + g[c]) / 0.7f;
    }
    float m2 = t[0];
#pragma unroll
    for (int c = 1; c < 8; c++) m2 = fmaxf(m2, t[c]);
    float e2[8], s2 = 0.0f;
#pragma unroll
    for (int c = 0; c < 8; c++) { e2[c] = expf(t[c] - m2); s2 += e2[c]; }
#pragma unroll
    for (int c = 0; c < 8; c++) xt[c] = e2[c] / s2;
}

__global__ void finalize_kernel(const float* __restrict__ x,
                                const float* __restrict__ Pm,
                                const float* __restrict__ W,
                                const float* __restrict__ truth,
                                const float* __restrict__ ea_b,
                                const float* __restrict__ eb_b,
                                const float* __restrict__ gum,
                                float* __restrict__ out_truth,
                                float* __restrict__ xcf) {
    const int b = blockIdx.x;
    const int n = threadIdx.x;
    __shared__ float sh_cst, sh_incr;

    const size_t base = (size_t)b * DD + n * CC;

    *reinterpret_cast<float4*>(out_truth + base) =
        *reinterpret_cast<const float4*>(truth + base);
    *reinterpret_cast<float4*>(out_truth + base + 4) =
        *reinterpret_cast<const float4*>(truth + base + 4);

    float4 xa = *reinterpret_cast<const float4*>(x + base);
    float4 xb = *reinterpret_cast<const float4*>(x + base + 4);
    float4 wa = *reinterpret_cast<const float4*>(W + base);
    float4 wb = *reinterpret_cast<const float4*>(W + base + 4);
    float xv[8] = {xa.x, xa.y, xa.z, xa.w, xb.x, xb.y, xb.z, xb.w};
    float Wv[8] = {wa.x, wa.y, wa.z, wa.w, wb.x, wb.y, wb.z, wb.w};

    const unsigned i = (unsigned)(b * NN + n);
    const float P = Pm[i];

    const float ea = ea_b[i];
    const float eb = eb_b[i];
    float no = P * ea / 0.7f;
    float de = no + (1.0f - P) * eb / 0.7f;
    float probs = no / de;

    float g[8];
    {
        float4 ga = *reinterpret_cast<const float4*>(gum + (size_t)i * 8);
        float4 gb = *reinterpret_cast<const float4*>(gum + (size_t)i * 8 + 4);
        g[0] = ga.x; g[1] = ga.y; g[2] = ga.z; g[3] = ga.w;
        g[4] = gb.x; g[5] = gb.y; g[6] = gb.z; g[7] = gb.w;
    }

    int curr = 0;
    {
        float m = xv[0];
#pragma unroll
        for (int c = 1; c < 8; c++)
            if (xv[c] > m) { m = xv[c]; curr = c; }
    }

    if (n == 2) {
        float xt_par[8];
        gs8(Wv, g, xt_par);
        int am = 0;
        float m = probs * xt_par[0] + (1.0f - probs) * xv[0];
#pragma unroll
        for (int c = 1; c < 8; c++) {
            float v = probs * xt_par[c] + (1.0f - probs) * xv[c];
            if (v > m) { m = v; am = c; }
        }
        int diff = am - curr;
        sh_cst  = (diff == 0) ? 1.0f : 0.0f;
        sh_incr = (diff >  0) ? 1.0f : 0.0f;
    }
    __syncthreads();
    const float cst = sh_cst;
    const float incr = sh_incr;

    float l[8];
    if (n == 0 || n == 5 || n == 10) {
#pragma unroll
        for (int c = 0; c < 8; c++) l[c] = Wv[c] + ((c < curr) ? -100.0f : 1.0f);
    } else if (n == 7) {
        const int thr = curr + 1;
        const bool inc = (incr > 0.5f);
#pragma unroll
        for (int c = 0; c < 8; c++)
            l[c] = Wv[c] + ((inc && c < thr) ? -100.0f : 1.0f);
    } else {
#pragma unroll
        for (int c = 0; c < 8; c++) l[c] = Wv[c];
    }

    float xt[8];
    gs8(l, g, xt);

    float p2 = probs;
    if (n == 7) {
        float pc = probs * (1.0f - cst);
        pc = pc + incr;
        p2 = fminf(fmaxf(pc, 0.0f), 1.0f);
    }

    float4 oa, ob;
    float* op = &oa.x;
#pragma unroll
    for (int c = 0; c < 4; c++) op[c] = p2 * xt[c] + (1.0f - p2) * xv[c];
    op = &ob.x;
#pragma unroll
    for (int c = 0; c < 4; c++) op[c] = p2 * xt[c + 4] + (1.0f - p2) * xv[c + 4];
    *reinterpret_cast<float4*>(xcf + base) = oa;
    *reinterpret_cast<float4*>(xcf + base + 4) = ob;
}

// ---------------------------------------------------------------------------
// Launch
// ---------------------------------------------------------------------------
extern "C" void kernel_launch(void* const* d_in, const int* in_sizes, int n_in,
                              void* d_out, int out_size) {
    const float* x     = (const float*)d_in[0];
    const float* truth = (const float*)d_in[1];
    const float* sw1   = (const float*)d_in[2];
    const float* sb1   = (const float*)d_in[3];
    const float* sw2   = (const float*)d_in[4];
    const float* sb2   = (const float*)d_in[5];
    const float* pw1   = (const float*)d_in[6];
    const float* pb1   = (const float*)d_in[7];
    const float* pw2   = (const float*)d_in[8];
    const float* pb2   = (const float*)d_in[9];
    const float* pw3   = (const float*)d_in[10];
    const float* pb3   = (const float*)d_in[11];
    const float* pw4   = (const float*)d_in[12];
    const float* pb4   = (const float*)d_in[13];

    float* out       = (float*)d_out;
    float* out_truth = out;
    float* out_xcf   = out + BD_ELEMS;
    float* out_P     = out + 2 * (size_t)BD_ELEMS;
    float* out_W     = out + 2 * (size_t)BD_ELEMS + BN_ELEMS;

    __half *a_hi, *a_lo, *b_hi, *b_lo, *xh, *wt_hi, *wt_lo;
    float *s1, *bias_l1, *ea, *eb, *gum;
    cudaGetSymbolAddress((void**)&a_hi, g_a_hi);
    cudaGetSymbolAddress((void**)&a_lo, g_a_lo);
    cudaGetSymbolAddress((void**)&b_hi, g_b_hi);
    cudaGetSymbolAddress((void**)&b_lo, g_b_lo);
    cudaGetSymbolAddress((void**)&xh,   g_xh);
    cudaGetSymbolAddress((void**)&s1,   g_s1);
    cudaGetSymbolAddress((void**)&wt_hi, g_wt_hi);
    cudaGetSymbolAddress((void**)&wt_lo, g_wt_lo);
    cudaGetSymbolAddress((void**)&bias_l1, g_bias_l1);
    cudaGetSymbolAddress((void**)&ea, g_ea);
    cudaGetSymbolAddress((void**)&eb, g_eb);
    cudaGetSymbolAddress((void**)&gum, g_gum);

    constexpr int SM4 = TileCfg<4>::SMEM;   // 73728
    constexpr int SM2 = TileCfg<2>::SMEM;   // 49152
    cudaFuncSetAttribute(gemm1_kernel,
                         cudaFuncAttributeMaxDynamicSharedMemorySize, SM4);
    cudaFuncSetAttribute(gemm_h<false, 0, 4>,
                         cudaFuncAttributeMaxDynamicSharedMemorySize, SM4);
    cudaFuncSetAttribute(gemm_h<false, 1, 2>,
                         cudaFuncAttributeMaxDynamicSharedMemorySize, SM2);
    cudaFuncSetAttribute(gemm2_head_kernel,
                         cudaFuncAttributeMaxDynamicSharedMemorySize, SM4);

    // Prep 1: x->fp16 + bias concat + pw1/sw1 splits only
    prep1_kernel<<<2816, 256>>>(x, xh, pb1, sb1, bias_l1, pw1, sw1, wt_hi,
                                wt_lo);

    // L1 GEMM fused with pw2-4 weight-split filler
    gemm1_kernel<<<dim3(12, 128 + 214), 256, SM4>>>(
        xh, wt_hi, wt_lo, bias_l1, a_hi, a_lo, s1,
        pw1, sw1, pw2, pw3, pw4, wt_hi, wt_lo);

    // gemm2 FUSED with selector head + RNG precompute
    gemm2_head_kernel<<<dim3(HP / 128, BB / 64 + 32 + 256), 256, SM4>>>(
        a_hi, a_lo, wt_hi + OF_PW2, wt_lo + OF_PW2, pb2, b_hi, b_lo,
        s1, sw2, sb2, out_P, ea, eb, gum);

    // gemm3 (NF=4), gemm4 (NF=2)
    gemm_h<false, 0, 4><<<dim3(HP / 128, BB / 64), 256, SM4>>>(
        b_hi, b_lo, wt_hi + OF_PW3, wt_lo + OF_PW3, pb3, a_hi, a_lo, nullptr,
        HP, HP);
    gemm_h<false, 1, 2><<<dim3(DD / 64, BB / 64), 256, SM2>>>(
        a_hi, a_lo, wt_hi + OF_PW4, wt_lo + OF_PW4, pb4, nullptr, nullptr,
        out_W, HP, DD);

    // Fused tail (+ truth passthrough), RNG from buffers
    finalize_kernel<<<BB, NN>>>(x, out_P, out_W, truth, ea, eb, gum,
                                out_truth, out_xcf);
}